// round 1
// baseline (speedup 1.0000x reference)
#include <cuda_runtime.h>
#include <cstdint>
#include <cstddef>

#define BB  128
#define TT  256
#define CC  384
#define HH  6
#define DD  64
#define LDQKV (3*CC)   // 1152

typedef unsigned long long u64;

// Scratch (device globals: allocation-free per harness rules)
__device__ float g_qkv[(size_t)BB * TT * 3 * CC];  // [32768][1152]
__device__ float g_att[(size_t)BB * TT * CC];      // [32768][384]

// ---------- packed fp32x2 helpers ----------
__device__ __forceinline__ u64 pk2(float lo, float hi) {
    u64 r; asm("mov.b64 %0, {%1, %2};" : "=l"(r) : "f"(lo), "f"(hi)); return r;
}
__device__ __forceinline__ void upk2(u64 v, float& lo, float& hi) {
    asm("mov.b64 {%0, %1}, %2;" : "=f"(lo), "=f"(hi) : "l"(v));
}
__device__ __forceinline__ void ffma2(u64& d, u64 a, u64 b) {
    asm("fma.rn.f32x2 %0, %1, %2, %0;" : "+l"(d) : "l"(a), "l"(b));
}

// ============================================================
// GEMM: C[M,N] = A[M,K] @ B[K,N], all row-major fp32.
// 128x128 block tile, BK=16, 256 threads, 8x8 micro-tile via FFMA2
// (accumulator pairs along M). Requires M%128==0, N%128==0, K%16==0.
// ============================================================
__global__ __launch_bounds__(256)
void gemm128_f32(const float* __restrict__ A, const float* __restrict__ Bm,
                 float* __restrict__ Cm, int M, int N, int K)
{
    __shared__ __align__(16) float As[16][128];  // transposed: As[k][m]
    __shared__ __align__(16) float Bs[16][128];  // Bs[k][n]

    const int tid = threadIdx.x;
    const int bm = blockIdx.y * 128;
    const int bn = blockIdx.x * 128;

    const int tm = (tid >> 4) * 8;   // micro-tile row base (0..120)
    const int tn = (tid & 15) * 8;   // micro-tile col base

    const int arow = tid >> 1;        // 0..127
    const int ak   = (tid & 1) * 8;   // 0 or 8
    const int brow = tid >> 4;        // 0..15
    const int bcol = (tid & 15) * 8;  // 0..120

    const float* Ap = A  + (size_t)(bm + arow) * K + ak;
    const float* Bp = Bm + (size_t)brow * N + (bn + bcol);

    u64 acc[4][8];
    #pragma unroll
    for (int i = 0; i < 4; i++)
        #pragma unroll
        for (int j = 0; j < 8; j++) acc[i][j] = 0ull;

    const int KT = K >> 4;
    float4 a0n = *(const float4*)(Ap);
    float4 a1n = *(const float4*)(Ap + 4);
    float4 b0n = *(const float4*)(Bp);
    float4 b1n = *(const float4*)(Bp + 4);

    for (int kt = 0; kt < KT; kt++) {
        __syncthreads();  // previous tile fully consumed
        As[ak+0][arow] = a0n.x; As[ak+1][arow] = a0n.y;
        As[ak+2][arow] = a0n.z; As[ak+3][arow] = a0n.w;
        As[ak+4][arow] = a1n.x; As[ak+5][arow] = a1n.y;
        As[ak+6][arow] = a1n.z; As[ak+7][arow] = a1n.w;
        *(float4*)&Bs[brow][bcol]     = b0n;
        *(float4*)&Bs[brow][bcol + 4] = b1n;
        __syncthreads();

        if (kt + 1 < KT) {  // prefetch next tile into registers (overlaps compute)
            const float* Ap2 = Ap + (size_t)(kt + 1) * 16;
            a0n = *(const float4*)(Ap2);
            a1n = *(const float4*)(Ap2 + 4);
            const float* Bp2 = Bp + (size_t)(kt + 1) * 16 * N;
            b0n = *(const float4*)(Bp2);
            b1n = *(const float4*)(Bp2 + 4);
        }

        #pragma unroll
        for (int k = 0; k < 16; k++) {
            u64 a0 = *(const u64*)&As[k][tm + 0];
            u64 a1 = *(const u64*)&As[k][tm + 2];
            u64 a2 = *(const u64*)&As[k][tm + 4];
            u64 a3 = *(const u64*)&As[k][tm + 6];
            float4 bq0 = *(const float4*)&Bs[k][tn];
            float4 bq1 = *(const float4*)&Bs[k][tn + 4];
            u64 bd[8];
            bd[0] = pk2(bq0.x, bq0.x); bd[1] = pk2(bq0.y, bq0.y);
            bd[2] = pk2(bq0.z, bq0.z); bd[3] = pk2(bq0.w, bq0.w);
            bd[4] = pk2(bq1.x, bq1.x); bd[5] = pk2(bq1.y, bq1.y);
            bd[6] = pk2(bq1.z, bq1.z); bd[7] = pk2(bq1.w, bq1.w);
            #pragma unroll
            for (int ni = 0; ni < 8; ni++) {
                ffma2(acc[0][ni], a0, bd[ni]);
                ffma2(acc[1][ni], a1, bd[ni]);
                ffma2(acc[2][ni], a2, bd[ni]);
                ffma2(acc[3][ni], a3, bd[ni]);
            }
        }
    }

    #pragma unroll
    for (int mi = 0; mi < 4; mi++) {
        float lo[8], hi[8];
        #pragma unroll
        for (int ni = 0; ni < 8; ni++) upk2(acc[mi][ni], lo[ni], hi[ni]);
        size_t r0 = (size_t)(bm + tm + 2 * mi) * N + bn + tn;
        *(float4*)&Cm[r0]         = make_float4(lo[0], lo[1], lo[2], lo[3]);
        *(float4*)&Cm[r0 + 4]     = make_float4(lo[4], lo[5], lo[6], lo[7]);
        *(float4*)&Cm[r0 + N]     = make_float4(hi[0], hi[1], hi[2], hi[3]);
        *(float4*)&Cm[r0 + N + 4] = make_float4(hi[4], hi[5], hi[6], hi[7]);
    }
}

// ============================================================
// Fused causal attention per (b, h). qkv layout: [b*T + t][3C]
// with column split order K | Q | V (reference splits K,Q,V).
// Block = one (b,h): stage K^T[64][256], V[256][64] in smem;
// loop 4 q-tiles of 64 rows: QK^T (FFMA2 micro-GEMM) -> causal
// softmax (unnormalized, 1/sum deferred) -> PV (k-loop truncated
// at causal boundary) -> scaled write to g_att[token][h*64+d].
// ============================================================
#define SPAD 66
#define ATTN_SMEM_FLOATS (64*256 + 256*64 + 64*64 + 256*SPAD + 64)
#define ATTN_SMEM_BYTES  (ATTN_SMEM_FLOATS * 4)

__global__ __launch_bounds__(256)
void attn_kernel(const float* __restrict__ qkv, float* __restrict__ att)
{
    extern __shared__ __align__(16) float sm[];
    float* Kt   = sm;                  // [64][256]  Kt[d][j]
    float* Vs   = Kt  + 64 * 256;      // [256][64]  Vs[j][d]
    float* Qst  = Vs  + 256 * 64;      // [64][64]   Qst[d][qi]
    float* St   = Qst + 64 * 64;       // [256][66]  St[j][qi]  (scores^T)
    float* rsum = St  + 256 * SPAD;    // [64]

    const int tid = threadIdx.x;
    const int b = blockIdx.x / HH;
    const int h = blockIdx.x % HH;
    const float* base = qkv + (size_t)b * TT * LDQKV;
    const float scale = 0.05103103630798288f;  // 384^-0.5 (full-embed quirk)

    // Stage K (transposed) and V
    {
        const int d4 = (tid & 15) * 4;
        for (int tok = tid >> 4; tok < TT; tok += 16) {
            const float* row = base + (size_t)tok * LDQKV + h * DD + d4;
            float4 kv = *(const float4*)(row);            // K at offset 0
            Kt[(d4+0)*TT + tok] = kv.x; Kt[(d4+1)*TT + tok] = kv.y;
            Kt[(d4+2)*TT + tok] = kv.z; Kt[(d4+3)*TT + tok] = kv.w;
            *(float4*)&Vs[tok*DD + d4] = *(const float4*)(row + 2*CC);  // V
        }
    }

    for (int qt = 0; qt < 4; qt++) {
        __syncthreads();
        // Stage Q tile transposed
        {
            const int d4 = (tid & 15) * 4;
            #pragma unroll
            for (int qi = tid >> 4; qi < 64; qi += 16) {
                float4 qv = *(const float4*)(base + (size_t)(qt*64 + qi) * LDQKV
                                             + CC + h * DD + d4);   // Q at offset C
                Qst[(d4+0)*64 + qi] = qv.x; Qst[(d4+1)*64 + qi] = qv.y;
                Qst[(d4+2)*64 + qi] = qv.z; Qst[(d4+3)*64 + qi] = qv.w;
            }
        }
        __syncthreads();

        // ---- QK^T: S[qi][j] = sum_d Qst[d][qi]*Kt[d][j], 8x8 micro ----
        {
            const int tm = (tid >> 5) * 8;   // qi base (8 groups)
            const int tn = (tid & 31) * 8;   // j  base (32 groups)
            u64 acc[4][8];
            #pragma unroll
            for (int i = 0; i < 4; i++)
                #pragma unroll
                for (int j = 0; j < 8; j++) acc[i][j] = 0ull;

            #pragma unroll 8
            for (int d = 0; d < 64; d++) {
                u64 a0 = *(const u64*)&Qst[d*64 + tm + 0];
                u64 a1 = *(const u64*)&Qst[d*64 + tm + 2];
                u64 a2 = *(const u64*)&Qst[d*64 + tm + 4];
                u64 a3 = *(const u64*)&Qst[d*64 + tm + 6];
                float4 bq0 = *(const float4*)&Kt[d*TT + tn];
                float4 bq1 = *(const float4*)&Kt[d*TT + tn + 4];
                u64 bd[8];
                bd[0] = pk2(bq0.x, bq0.x); bd[1] = pk2(bq0.y, bq0.y);
                bd[2] = pk2(bq0.z, bq0.z); bd[3] = pk2(bq0.w, bq0.w);
                bd[4] = pk2(bq1.x, bq1.x); bd[5] = pk2(bq1.y, bq1.y);
                bd[6] = pk2(bq1.z, bq1.z); bd[7] = pk2(bq1.w, bq1.w);
                #pragma unroll
                for (int ni = 0; ni < 8; ni++) {
                    ffma2(acc[0][ni], a0, bd[ni]);
                    ffma2(acc[1][ni], a1, bd[ni]);
                    ffma2(acc[2][ni], a2, bd[ni]);
                    ffma2(acc[3][ni], a3, bd[ni]);
                }
            }
            #pragma unroll
            for (int mi = 0; mi < 4; mi++)
                #pragma unroll
                for (int ni = 0; ni < 8; ni++) {
                    float lo, hi; upk2(acc[mi][ni], lo, hi);
                    St[(tn+ni)*SPAD + tm + 2*mi]     = lo;
                    St[(tn+ni)*SPAD + tm + 2*mi + 1] = hi;
                }
        }
        __syncthreads();

        // ---- causal softmax (per row; 1/sum deferred to epilogue) ----
        {
            const int w = tid >> 5, lane = tid & 31;
            const int nj = (qt + 1) * 64;
            for (int qi = w * 8; qi < w * 8 + 8; qi++) {
                const int nv = qt * 64 + qi + 1;   // valid j in [0, nv)
                float m = -1e30f;
                for (int j = lane; j < nv; j += 32) m = fmaxf(m, St[j*SPAD + qi]);
                #pragma unroll
                for (int o = 16; o; o >>= 1) m = fmaxf(m, __shfl_xor_sync(0xffffffffu, m, o));
                m *= scale;
                float s = 0.f;
                for (int j = lane; j < nj; j += 32) {
                    float p = (j < nv) ? __expf(St[j*SPAD + qi] * scale - m) : 0.f;
                    St[j*SPAD + qi] = p;
                    s += p;
                }
                #pragma unroll
                for (int o = 16; o; o >>= 1) s += __shfl_xor_sync(0xffffffffu, s, o);
                if (lane == 0) rsum[qi] = 1.f / s;
            }
        }
        __syncthreads();

        // ---- PV: O[qi][n] = sum_j St[j][qi]*Vs[j][n], 4x4 micro ----
        {
            const int tm = (tid >> 4) * 4;   // qi base
            const int tn = (tid & 15) * 4;   // n  base
            const int nj = (qt + 1) * 64;    // causal truncation
            u64 acc[2][4];
            #pragma unroll
            for (int i = 0; i < 2; i++)
                #pragma unroll
                for (int j = 0; j < 4; j++) acc[i][j] = 0ull;

            #pragma unroll 4
            for (int j = 0; j < nj; j++) {
                u64 a0 = *(const u64*)&St[j*SPAD + tm];
                u64 a1 = *(const u64*)&St[j*SPAD + tm + 2];
                float4 bq = *(const float4*)&Vs[j*DD + tn];
                u64 b0 = pk2(bq.x, bq.x), b1 = pk2(bq.y, bq.y);
                u64 b2 = pk2(bq.z, bq.z), b3 = pk2(bq.w, bq.w);
                ffma2(acc[0][0], a0, b0); ffma2(acc[0][1], a0, b1);
                ffma2(acc[0][2], a0, b2); ffma2(acc[0][3], a0, b3);
                ffma2(acc[1][0], a1, b0); ffma2(acc[1][1], a1, b1);
                ffma2(acc[1][2], a1, b2); ffma2(acc[1][3], a1, b3);
            }
            #pragma unroll
            for (int p = 0; p < 2; p++) {
                float lo[4], hi[4];
                #pragma unroll
                for (int ni = 0; ni < 4; ni++) upk2(acc[p][ni], lo[ni], hi[ni]);
                const int qi0 = tm + 2 * p;
                const float s0 = rsum[qi0], s1 = rsum[qi0 + 1];
                size_t r = ((size_t)b * TT + qt*64 + qi0) * CC + h * DD + tn;
                *(float4*)&att[r]      = make_float4(lo[0]*s0, lo[1]*s0, lo[2]*s0, lo[3]*s0);
                *(float4*)&att[r + CC] = make_float4(hi[0]*s1, hi[1]*s1, hi[2]*s1, hi[3]*s1);
            }
        }
    }
}

// ============================================================
extern "C" void kernel_launch(void* const* d_in, const int* in_sizes, int n_in,
                              void* d_out, int out_size)
{
    const float* X     = (const float*)d_in[0];
    const float* Wqkv  = (const float*)d_in[1];
    const float* Wproj = (const float*)d_in[2];
    float* out = (float*)d_out;

    void *p0, *p1;
    cudaGetSymbolAddress(&p0, g_qkv);
    cudaGetSymbolAddress(&p1, g_att);
    float* qkv = (float*)p0;
    float* att = (float*)p1;

    cudaFuncSetAttribute(attn_kernel, cudaFuncAttributeMaxDynamicSharedMemorySize,
                         ATTN_SMEM_BYTES);

    // 1) qkv = X @ Wqkv     [32768,1152] = [32768,384]@[384,1152]
    dim3 g1(3 * CC / 128, BB * TT / 128);       // (9, 256)
    gemm128_f32<<<g1, 256>>>(X, Wqkv, qkv, BB * TT, 3 * CC, CC);

    // 2) fused causal attention -> att [32768,384]
    attn_kernel<<<BB * HH, 256, ATTN_SMEM_BYTES>>>(qkv, att);

    // 3) out = att @ Wproj  [32768,384] = [32768,384]@[384,384]
    dim3 g3(CC / 128, BB * TT / 128);           // (3, 256)
    gemm128_f32<<<g3, 256>>>(att, Wproj, out, BB * TT, CC, CC);
}

// round 2
// speedup vs baseline: 1.2378x; 1.2378x over previous
#include <cuda_runtime.h>
#include <cstdint>
#include <cstddef>

#define BB  128
#define TT  256
#define CC  384
#define HH  6
#define DD  64
#define LDQKV (3*CC)   // 1152

typedef unsigned long long u64;

// Scratch (device globals: allocation-free per harness rules)
__device__ float g_qkv[(size_t)BB * TT * 3 * CC];  // [32768][1152]
__device__ float g_att[(size_t)BB * TT * CC];      // [32768][384]

// ---------- packed fp32x2 helpers (attention kernel) ----------
__device__ __forceinline__ u64 pk2(float lo, float hi) {
    u64 r; asm("mov.b64 %0, {%1, %2};" : "=l"(r) : "f"(lo), "f"(hi)); return r;
}
__device__ __forceinline__ void upk2(u64 v, float& lo, float& hi) {
    asm("mov.b64 {%0, %1}, %2;" : "=f"(lo), "=f"(hi) : "l"(v));
}
__device__ __forceinline__ void ffma2(u64& d, u64 a, u64 b) {
    asm("fma.rn.f32x2 %0, %1, %2, %0;" : "+l"(d) : "l"(a), "l"(b));
}

// ---------- tf32 helpers ----------
__device__ __forceinline__ float tf32_big(float f) {
    uint32_t r; asm("cvt.rna.tf32.f32 %0, %1;" : "=r"(r) : "f"(f));
    return __uint_as_float(r);
}
__device__ __forceinline__ void mma8(float* c, const uint32_t* a, const uint32_t* b) {
    asm volatile("mma.sync.aligned.m16n8k8.row.col.f32.tf32.tf32.f32 "
        "{%0,%1,%2,%3}, {%4,%5,%6,%7}, {%8,%9}, {%0,%1,%2,%3};"
        : "+f"(c[0]), "+f"(c[1]), "+f"(c[2]), "+f"(c[3])
        : "r"(a[0]), "r"(a[1]), "r"(a[2]), "r"(a[3]), "r"(b[0]), "r"(b[1]));
}

// ============================================================
// GEMM via 3xTF32 tensor-core mma: C[M,N]=A[M,K]@B[K,N] fp32.
// Block 128x128, BK=32, 512 threads (16 warps, warp tile 32x32).
// A/B split into (big tf32, small residual) at smem-store time;
// inner loop: 3 mma passes (bb, b*s, s*b) -> fp32-accurate.
// Requires M%128==0, N%128==0, K%32==0.
// ============================================================
#define ASTRIDE 36
#define BSTRIDE 136
#define GEMM_SMEM_FLOATS (2*128*ASTRIDE + 2*32*BSTRIDE)   // 17920
#define GEMM_SMEM_BYTES  (GEMM_SMEM_FLOATS * 4)           // 71680

__global__ __launch_bounds__(512, 1)
void gemm_tf32x3(const float* __restrict__ A, const float* __restrict__ B,
                 float* __restrict__ Cm, int M, int N, int K)
{
    extern __shared__ __align__(16) float sm[];
    float* Ab = sm;                       // [128][36]  big
    float* Al = Ab + 128 * ASTRIDE;       // [128][36]  small
    float* Bb = Al + 128 * ASTRIDE;       // [32][136]  big
    float* Bl = Bb + 32 * BSTRIDE;        // [32][136]  small

    const int tid  = threadIdx.x;
    const int lane = tid & 31;
    const int warp = tid >> 5;
    const int bm = blockIdx.y * 128;
    const int bn = blockIdx.x * 128;
    const int wm = (warp >> 2) * 32;
    const int wn = (warp & 3) * 32;

    // global->smem mapping
    const int arow = tid >> 2;            // 0..127
    const int acol = (tid & 3) * 8;       // 0,8,16,24
    const int bk   = tid >> 4;            // 0..31
    const int bn0  = (tid & 15) * 8;      // 0..120

    const float* Ap = A + (size_t)(bm + arow) * K + acol;
    const float* Bp = B + (size_t)bk * N + bn + bn0;

    float acc[2][4][4];
    #pragma unroll
    for (int i = 0; i < 2; i++)
        #pragma unroll
        for (int j = 0; j < 4; j++)
            #pragma unroll
            for (int l = 0; l < 4; l++) acc[i][j][l] = 0.f;

    const int KT = K >> 5;
    float4 ra0 = *(const float4*)(Ap);
    float4 ra1 = *(const float4*)(Ap + 4);
    float4 rb0 = *(const float4*)(Bp);
    float4 rb1 = *(const float4*)(Bp + 4);

    const int g = lane >> 2;   // 0..7
    const int t = lane & 3;    // 0..3

    for (int kt = 0; kt < KT; kt++) {
        __syncthreads();
        // split + store A tile
        {
            float4 hb, hl;
            hb.x = tf32_big(ra0.x); hl.x = ra0.x - hb.x;
            hb.y = tf32_big(ra0.y); hl.y = ra0.y - hb.y;
            hb.z = tf32_big(ra0.z); hl.z = ra0.z - hb.z;
            hb.w = tf32_big(ra0.w); hl.w = ra0.w - hb.w;
            *(float4*)&Ab[arow * ASTRIDE + acol] = hb;
            *(float4*)&Al[arow * ASTRIDE + acol] = hl;
            hb.x = tf32_big(ra1.x); hl.x = ra1.x - hb.x;
            hb.y = tf32_big(ra1.y); hl.y = ra1.y - hb.y;
            hb.z = tf32_big(ra1.z); hl.z = ra1.z - hb.z;
            hb.w = tf32_big(ra1.w); hl.w = ra1.w - hb.w;
            *(float4*)&Ab[arow * ASTRIDE + acol + 4] = hb;
            *(float4*)&Al[arow * ASTRIDE + acol + 4] = hl;
            // split + store B tile
            hb.x = tf32_big(rb0.x); hl.x = rb0.x - hb.x;
            hb.y = tf32_big(rb0.y); hl.y = rb0.y - hb.y;
            hb.z = tf32_big(rb0.z); hl.z = rb0.z - hb.z;
            hb.w = tf32_big(rb0.w); hl.w = rb0.w - hb.w;
            *(float4*)&Bb[bk * BSTRIDE + bn0] = hb;
            *(float4*)&Bl[bk * BSTRIDE + bn0] = hl;
            hb.x = tf32_big(rb1.x); hl.x = rb1.x - hb.x;
            hb.y = tf32_big(rb1.y); hl.y = rb1.y - hb.y;
            hb.z = tf32_big(rb1.z); hl.z = rb1.z - hb.z;
            hb.w = tf32_big(rb1.w); hl.w = rb1.w - hb.w;
            *(float4*)&Bb[bk * BSTRIDE + bn0 + 4] = hb;
            *(float4*)&Bl[bk * BSTRIDE + bn0 + 4] = hl;
        }
        __syncthreads();

        if (kt + 1 < KT) {   // prefetch next tile
            const float* Ap2 = Ap + (kt + 1) * 32;
            ra0 = *(const float4*)(Ap2);
            ra1 = *(const float4*)(Ap2 + 4);
            const float* Bp2 = Bp + (size_t)(kt + 1) * 32 * N;
            rb0 = *(const float4*)(Bp2);
            rb1 = *(const float4*)(Bp2 + 4);
        }

        #pragma unroll
        for (int s = 0; s < 4; s++) {
            const int kc = s * 8 + t;
            uint32_t afb[2][4], afl[2][4], bfb[4][2], bfl[4][2];
            #pragma unroll
            for (int mt = 0; mt < 2; mt++) {
                const int r0 = (wm + mt * 16 + g) * ASTRIDE + kc;
                afb[mt][0] = __float_as_uint(Ab[r0]);
                afb[mt][1] = __float_as_uint(Ab[r0 + 8 * ASTRIDE]);
                afb[mt][2] = __float_as_uint(Ab[r0 + 4]);
                afb[mt][3] = __float_as_uint(Ab[r0 + 8 * ASTRIDE + 4]);
                afl[mt][0] = __float_as_uint(Al[r0]);
                afl[mt][1] = __float_as_uint(Al[r0 + 8 * ASTRIDE]);
                afl[mt][2] = __float_as_uint(Al[r0 + 4]);
                afl[mt][3] = __float_as_uint(Al[r0 + 8 * ASTRIDE + 4]);
            }
            #pragma unroll
            for (int nt = 0; nt < 4; nt++) {
                const int c0 = kc * BSTRIDE + wn + nt * 8 + g;
                bfb[nt][0] = __float_as_uint(Bb[c0]);
                bfb[nt][1] = __float_as_uint(Bb[c0 + 4 * BSTRIDE]);
                bfl[nt][0] = __float_as_uint(Bl[c0]);
                bfl[nt][1] = __float_as_uint(Bl[c0 + 4 * BSTRIDE]);
            }
            #pragma unroll
            for (int mt = 0; mt < 2; mt++)
                #pragma unroll
                for (int nt = 0; nt < 4; nt++) {
                    mma8(acc[mt][nt], afb[mt], bfl[nt]);   // big*small
                    mma8(acc[mt][nt], afl[mt], bfb[nt]);   // small*big
                    mma8(acc[mt][nt], afb[mt], bfb[nt]);   // big*big
                }
        }
    }

    // epilogue
    #pragma unroll
    for (int mt = 0; mt < 2; mt++)
        #pragma unroll
        for (int nt = 0; nt < 4; nt++) {
            const int row = bm + wm + mt * 16 + g;
            const int col = bn + wn + nt * 8 + 2 * t;
            *(float2*)&Cm[(size_t)row * N + col] =
                make_float2(acc[mt][nt][0], acc[mt][nt][1]);
            *(float2*)&Cm[(size_t)(row + 8) * N + col] =
                make_float2(acc[mt][nt][2], acc[mt][nt][3]);
        }
}

// ============================================================
// Fused causal attention per (b, h). qkv layout: [b*T + t][3C]
// with column split order K | Q | V (reference splits K,Q,V).
// ============================================================
#define SPAD 66
#define ATTN_SMEM_FLOATS (64*256 + 256*64 + 64*64 + 256*SPAD + 64)
#define ATTN_SMEM_BYTES  (ATTN_SMEM_FLOATS * 4)

__global__ __launch_bounds__(256)
void attn_kernel(const float* __restrict__ qkv, float* __restrict__ att)
{
    extern __shared__ __align__(16) float sm[];
    float* Kt   = sm;                  // [64][256]  Kt[d][j]
    float* Vs   = Kt  + 64 * 256;      // [256][64]  Vs[j][d]
    float* Qst  = Vs  + 256 * 64;      // [64][64]   Qst[d][qi]
    float* St   = Qst + 64 * 64;       // [256][66]  St[j][qi]  (scores^T)
    float* rsum = St  + 256 * SPAD;    // [64]

    const int tid = threadIdx.x;
    const int b = blockIdx.x / HH;
    const int h = blockIdx.x % HH;
    const float* base = qkv + (size_t)b * TT * LDQKV;
    const float scale = 0.05103103630798288f;  // 384^-0.5 (full-embed quirk)

    // Stage K (transposed) and V
    {
        const int d4 = (tid & 15) * 4;
        for (int tok = tid >> 4; tok < TT; tok += 16) {
            const float* row = base + (size_t)tok * LDQKV + h * DD + d4;
            float4 kv = *(const float4*)(row);            // K at offset 0
            Kt[(d4+0)*TT + tok] = kv.x; Kt[(d4+1)*TT + tok] = kv.y;
            Kt[(d4+2)*TT + tok] = kv.z; Kt[(d4+3)*TT + tok] = kv.w;
            *(float4*)&Vs[tok*DD + d4] = *(const float4*)(row + 2*CC);  // V
        }
    }

    for (int qt = 0; qt < 4; qt++) {
        __syncthreads();
        // Stage Q tile transposed
        {
            const int d4 = (tid & 15) * 4;
            #pragma unroll
            for (int qi = tid >> 4; qi < 64; qi += 16) {
                float4 qv = *(const float4*)(base + (size_t)(qt*64 + qi) * LDQKV
                                             + CC + h * DD + d4);   // Q at offset C
                Qst[(d4+0)*64 + qi] = qv.x; Qst[(d4+1)*64 + qi] = qv.y;
                Qst[(d4+2)*64 + qi] = qv.z; Qst[(d4+3)*64 + qi] = qv.w;
            }
        }
        __syncthreads();

        // ---- QK^T: S[qi][j] = sum_d Qst[d][qi]*Kt[d][j], 8x8 micro ----
        {
            const int tm = (tid >> 5) * 8;   // qi base (8 groups)
            const int tn = (tid & 31) * 8;   // j  base (32 groups)
            u64 acc[4][8];
            #pragma unroll
            for (int i = 0; i < 4; i++)
                #pragma unroll
                for (int j = 0; j < 8; j++) acc[i][j] = 0ull;

            #pragma unroll 8
            for (int d = 0; d < 64; d++) {
                u64 a0 = *(const u64*)&Qst[d*64 + tm + 0];
                u64 a1 = *(const u64*)&Qst[d*64 + tm + 2];
                u64 a2 = *(const u64*)&Qst[d*64 + tm + 4];
                u64 a3 = *(const u64*)&Qst[d*64 + tm + 6];
                float4 bq0 = *(const float4*)&Kt[d*TT + tn];
                float4 bq1 = *(const float4*)&Kt[d*TT + tn + 4];
                u64 bd[8];
                bd[0] = pk2(bq0.x, bq0.x); bd[1] = pk2(bq0.y, bq0.y);
                bd[2] = pk2(bq0.z, bq0.z); bd[3] = pk2(bq0.w, bq0.w);
                bd[4] = pk2(bq1.x, bq1.x); bd[5] = pk2(bq1.y, bq1.y);
                bd[6] = pk2(bq1.z, bq1.z); bd[7] = pk2(bq1.w, bq1.w);
                #pragma unroll
                for (int ni = 0; ni < 8; ni++) {
                    ffma2(acc[0][ni], a0, bd[ni]);
                    ffma2(acc[1][ni], a1, bd[ni]);
                    ffma2(acc[2][ni], a2, bd[ni]);
                    ffma2(acc[3][ni], a3, bd[ni]);
                }
            }
            #pragma unroll
            for (int mi = 0; mi < 4; mi++)
                #pragma unroll
                for (int ni = 0; ni < 8; ni++) {
                    float lo, hi; upk2(acc[mi][ni], lo, hi);
                    St[(tn+ni)*SPAD + tm + 2*mi]     = lo;
                    St[(tn+ni)*SPAD + tm + 2*mi + 1] = hi;
                }
        }
        __syncthreads();

        // ---- causal softmax (per row; 1/sum deferred to epilogue) ----
        {
            const int w = tid >> 5, lane = tid & 31;
            const int nj = (qt + 1) * 64;
            for (int qi = w * 8; qi < w * 8 + 8; qi++) {
                const int nv = qt * 64 + qi + 1;   // valid j in [0, nv)
                float m = -1e30f;
                for (int j = lane; j < nv; j += 32) m = fmaxf(m, St[j*SPAD + qi]);
                #pragma unroll
                for (int o = 16; o; o >>= 1) m = fmaxf(m, __shfl_xor_sync(0xffffffffu, m, o));
                m *= scale;
                float s = 0.f;
                for (int j = lane; j < nj; j += 32) {
                    float p = (j < nv) ? __expf(St[j*SPAD + qi] * scale - m) : 0.f;
                    St[j*SPAD + qi] = p;
                    s += p;
                }
                #pragma unroll
                for (int o = 16; o; o >>= 1) s += __shfl_xor_sync(0xffffffffu, s, o);
                if (lane == 0) rsum[qi] = 1.f / s;
            }
        }
        __syncthreads();

        // ---- PV: O[qi][n] = sum_j St[j][qi]*Vs[j][n], 4x4 micro ----
        {
            const int tm = (tid >> 4) * 4;   // qi base
            const int tn = (tid & 15) * 4;   // n  base
            const int nj = (qt + 1) * 64;    // causal truncation
            u64 acc[2][4];
            #pragma unroll
            for (int i = 0; i < 2; i++)
                #pragma unroll
                for (int j = 0; j < 4; j++) acc[i][j] = 0ull;

            #pragma unroll 4
            for (int j = 0; j < nj; j++) {
                u64 a0 = *(const u64*)&St[j*SPAD + tm];
                u64 a1 = *(const u64*)&St[j*SPAD + tm + 2];
                float4 bq = *(const float4*)&Vs[j*DD + tn];
                u64 b0 = pk2(bq.x, bq.x), b1 = pk2(bq.y, bq.y);
                u64 b2 = pk2(bq.z, bq.z), b3 = pk2(bq.w, bq.w);
                ffma2(acc[0][0], a0, b0); ffma2(acc[0][1], a0, b1);
                ffma2(acc[0][2], a0, b2); ffma2(acc[0][3], a0, b3);
                ffma2(acc[1][0], a1, b0); ffma2(acc[1][1], a1, b1);
                ffma2(acc[1][2], a1, b2); ffma2(acc[1][3], a1, b3);
            }
            #pragma unroll
            for (int p = 0; p < 2; p++) {
                float lo[4], hi[4];
                #pragma unroll
                for (int ni = 0; ni < 4; ni++) upk2(acc[p][ni], lo[ni], hi[ni]);
                const int qi0 = tm + 2 * p;
                const float s0 = rsum[qi0], s1 = rsum[qi0 + 1];
                size_t r = ((size_t)b * TT + qt*64 + qi0) * CC + h * DD + tn;
                *(float4*)&att[r]      = make_float4(lo[0]*s0, lo[1]*s0, lo[2]*s0, lo[3]*s0);
                *(float4*)&att[r + CC] = make_float4(hi[0]*s1, hi[1]*s1, hi[2]*s1, hi[3]*s1);
            }
        }
    }
}

// ============================================================
extern "C" void kernel_launch(void* const* d_in, const int* in_sizes, int n_in,
                              void* d_out, int out_size)
{
    const float* X     = (const float*)d_in[0];
    const float* Wqkv  = (const float*)d_in[1];
    const float* Wproj = (const float*)d_in[2];
    float* out = (float*)d_out;

    void *p0, *p1;
    cudaGetSymbolAddress(&p0, g_qkv);
    cudaGetSymbolAddress(&p1, g_att);
    float* qkv = (float*)p0;
    float* att = (float*)p1;

    cudaFuncSetAttribute(gemm_tf32x3, cudaFuncAttributeMaxDynamicSharedMemorySize,
                         GEMM_SMEM_BYTES);
    cudaFuncSetAttribute(attn_kernel, cudaFuncAttributeMaxDynamicSharedMemorySize,
                         ATTN_SMEM_BYTES);

    // 1) qkv = X @ Wqkv     [32768,1152] = [32768,384]@[384,1152]
    dim3 g1(3 * CC / 128, BB * TT / 128);       // (9, 256)
    gemm_tf32x3<<<g1, 512, GEMM_SMEM_BYTES>>>(X, Wqkv, qkv, BB * TT, 3 * CC, CC);

    // 2) fused causal attention -> att [32768,384]
    attn_kernel<<<BB * HH, 256, ATTN_SMEM_BYTES>>>(qkv, att);

    // 3) out = att @ Wproj  [32768,384] = [32768,384]@[384,384]
    dim3 g3(CC / 128, BB * TT / 128);           // (3, 256)
    gemm_tf32x3<<<g3, 512, GEMM_SMEM_BYTES>>>(att, Wproj, out, BB * TT, CC, CC);
}

// round 3
// speedup vs baseline: 1.4740x; 1.1909x over previous
#include <cuda_runtime.h>
#include <cstdint>
#include <cstddef>

#define BB  128
#define TT  256
#define CC  384
#define HH  6
#define DD  64
#define LDQKV (3*CC)   // 1152

typedef unsigned long long u64;

// Scratch (device globals: allocation-free per harness rules)
__device__ float g_qkv[(size_t)BB * TT * 3 * CC];  // [32768][1152]
__device__ float g_att[(size_t)BB * TT * CC];      // [32768][384]

// ---------- tf32 helpers ----------
__device__ __forceinline__ float tf32_big(float f) {
    uint32_t r; asm("cvt.rna.tf32.f32 %0, %1;" : "=r"(r) : "f"(f));
    return __uint_as_float(r);
}
__device__ __forceinline__ void mma8(float* c, const uint32_t* a, const uint32_t* b) {
    asm volatile("mma.sync.aligned.m16n8k8.row.col.f32.tf32.tf32.f32 "
        "{%0,%1,%2,%3}, {%4,%5,%6,%7}, {%8,%9}, {%0,%1,%2,%3};"
        : "+f"(c[0]), "+f"(c[1]), "+f"(c[2]), "+f"(c[3])
        : "r"(a[0]), "r"(a[1]), "r"(a[2]), "r"(a[3]), "r"(b[0]), "r"(b[1]));
}

// ============================================================
// GEMM via 3xTF32 tensor-core mma: C[M,N]=A[M,K]@B[K,N] fp32.
// Block 128x128, BK=32, 512 threads (16 warps, warp tile 32x32).
// ============================================================
#define ASTRIDE 36
#define BSTRIDE 136
#define GEMM_SMEM_FLOATS (2*128*ASTRIDE + 2*32*BSTRIDE)   // 17920
#define GEMM_SMEM_BYTES  (GEMM_SMEM_FLOATS * 4)           // 71680

__global__ __launch_bounds__(512, 1)
void gemm_tf32x3(const float* __restrict__ A, const float* __restrict__ B,
                 float* __restrict__ Cm, int M, int N, int K)
{
    extern __shared__ __align__(16) float sm[];
    float* Ab = sm;                       // [128][36]  big
    float* Al = Ab + 128 * ASTRIDE;       // [128][36]  small
    float* Bb = Al + 128 * ASTRIDE;       // [32][136]  big
    float* Bl = Bb + 32 * BSTRIDE;        // [32][136]  small

    const int tid  = threadIdx.x;
    const int lane = tid & 31;
    const int warp = tid >> 5;
    const int bm = blockIdx.y * 128;
    const int bn = blockIdx.x * 128;
    const int wm = (warp >> 2) * 32;
    const int wn = (warp & 3) * 32;

    const int arow = tid >> 2;            // 0..127
    const int acol = (tid & 3) * 8;       // 0,8,16,24
    const int bk   = tid >> 4;            // 0..31
    const int bn0  = (tid & 15) * 8;      // 0..120

    const float* Ap = A + (size_t)(bm + arow) * K + acol;
    const float* Bp = B + (size_t)bk * N + bn + bn0;

    float acc[2][4][4];
    #pragma unroll
    for (int i = 0; i < 2; i++)
        #pragma unroll
        for (int j = 0; j < 4; j++)
            #pragma unroll
            for (int l = 0; l < 4; l++) acc[i][j][l] = 0.f;

    const int KT = K >> 5;
    float4 ra0 = *(const float4*)(Ap);
    float4 ra1 = *(const float4*)(Ap + 4);
    float4 rb0 = *(const float4*)(Bp);
    float4 rb1 = *(const float4*)(Bp + 4);

    const int g = lane >> 2;   // 0..7
    const int t = lane & 3;    // 0..3

    for (int kt = 0; kt < KT; kt++) {
        __syncthreads();
        {
            float4 hb, hl;
            hb.x = tf32_big(ra0.x); hl.x = ra0.x - hb.x;
            hb.y = tf32_big(ra0.y); hl.y = ra0.y - hb.y;
            hb.z = tf32_big(ra0.z); hl.z = ra0.z - hb.z;
            hb.w = tf32_big(ra0.w); hl.w = ra0.w - hb.w;
            *(float4*)&Ab[arow * ASTRIDE + acol] = hb;
            *(float4*)&Al[arow * ASTRIDE + acol] = hl;
            hb.x = tf32_big(ra1.x); hl.x = ra1.x - hb.x;
            hb.y = tf32_big(ra1.y); hl.y = ra1.y - hb.y;
            hb.z = tf32_big(ra1.z); hl.z = ra1.z - hb.z;
            hb.w = tf32_big(ra1.w); hl.w = ra1.w - hb.w;
            *(float4*)&Ab[arow * ASTRIDE + acol + 4] = hb;
            *(float4*)&Al[arow * ASTRIDE + acol + 4] = hl;
            hb.x = tf32_big(rb0.x); hl.x = rb0.x - hb.x;
            hb.y = tf32_big(rb0.y); hl.y = rb0.y - hb.y;
            hb.z = tf32_big(rb0.z); hl.z = rb0.z - hb.z;
            hb.w = tf32_big(rb0.w); hl.w = rb0.w - hb.w;
            *(float4*)&Bb[bk * BSTRIDE + bn0] = hb;
            *(float4*)&Bl[bk * BSTRIDE + bn0] = hl;
            hb.x = tf32_big(rb1.x); hl.x = rb1.x - hb.x;
            hb.y = tf32_big(rb1.y); hl.y = rb1.y - hb.y;
            hb.z = tf32_big(rb1.z); hl.z = rb1.z - hb.z;
            hb.w = tf32_big(rb1.w); hl.w = rb1.w - hb.w;
            *(float4*)&Bb[bk * BSTRIDE + bn0 + 4] = hb;
            *(float4*)&Bl[bk * BSTRIDE + bn0 + 4] = hl;
        }
        __syncthreads();

        if (kt + 1 < KT) {
            const float* Ap2 = Ap + (kt + 1) * 32;
            ra0 = *(const float4*)(Ap2);
            ra1 = *(const float4*)(Ap2 + 4);
            const float* Bp2 = Bp + (size_t)(kt + 1) * 32 * N;
            rb0 = *(const float4*)(Bp2);
            rb1 = *(const float4*)(Bp2 + 4);
        }

        #pragma unroll
        for (int s = 0; s < 4; s++) {
            const int kc = s * 8 + t;
            uint32_t afb[2][4], afl[2][4], bfb[4][2], bfl[4][2];
            #pragma unroll
            for (int mt = 0; mt < 2; mt++) {
                const int r0 = (wm + mt * 16 + g) * ASTRIDE + kc;
                afb[mt][0] = __float_as_uint(Ab[r0]);
                afb[mt][1] = __float_as_uint(Ab[r0 + 8 * ASTRIDE]);
                afb[mt][2] = __float_as_uint(Ab[r0 + 4]);
                afb[mt][3] = __float_as_uint(Ab[r0 + 8 * ASTRIDE + 4]);
                afl[mt][0] = __float_as_uint(Al[r0]);
                afl[mt][1] = __float_as_uint(Al[r0 + 8 * ASTRIDE]);
                afl[mt][2] = __float_as_uint(Al[r0 + 4]);
                afl[mt][3] = __float_as_uint(Al[r0 + 8 * ASTRIDE + 4]);
            }
            #pragma unroll
            for (int nt = 0; nt < 4; nt++) {
                const int c0 = kc * BSTRIDE + wn + nt * 8 + g;
                bfb[nt][0] = __float_as_uint(Bb[c0]);
                bfb[nt][1] = __float_as_uint(Bb[c0 + 4 * BSTRIDE]);
                bfl[nt][0] = __float_as_uint(Bl[c0]);
                bfl[nt][1] = __float_as_uint(Bl[c0 + 4 * BSTRIDE]);
            }
            #pragma unroll
            for (int mt = 0; mt < 2; mt++)
                #pragma unroll
                for (int nt = 0; nt < 4; nt++) {
                    mma8(acc[mt][nt], afb[mt], bfl[nt]);
                    mma8(acc[mt][nt], afl[mt], bfb[nt]);
                    mma8(acc[mt][nt], afb[mt], bfb[nt]);
                }
        }
    }

    #pragma unroll
    for (int mt = 0; mt < 2; mt++)
        #pragma unroll
        for (int nt = 0; nt < 4; nt++) {
            const int row = bm + wm + mt * 16 + g;
            const int col = bn + wn + nt * 8 + 2 * t;
            *(float2*)&Cm[(size_t)row * N + col] =
                make_float2(acc[mt][nt][0], acc[mt][nt][1]);
            *(float2*)&Cm[(size_t)(row + 8) * N + col] =
                make_float2(acc[mt][nt][2], acc[mt][nt][3]);
        }
}

// ============================================================
// Tensor-core fused causal attention per (b, h).
// qkv layout: [b*T+t][3C], split order K | Q | V.
// 256 threads = 8 warps (2 m x 4 n). 1xTF32 (rna at staging).
// smem: Kt[64][264] (K^T), Vs[256][72], Ps[64][260], Qs[64][68].
// Per q-tile of 64 rows: QK^T mma (skip above-diagonal warp
// cols) -> softmax (row-major, tf32-round P) -> PV mma (k
// truncated at causal boundary) -> scaled write.
// ============================================================
#define KTS 264
#define VSS 72
#define PSS 260
#define QSS 68
#define ATTN_SMEM_FLOATS (64*KTS + 256*VSS + 64*PSS + 64*QSS + 64)  // 56384
#define ATTN_SMEM_BYTES  (ATTN_SMEM_FLOATS * 4)                      // 225536

__global__ __launch_bounds__(256, 1)
void attn_kernel(const float* __restrict__ qkv, float* __restrict__ att)
{
    extern __shared__ __align__(16) float sm[];
    float* Kt   = sm;                   // [64][264]   Kt[d][tok]
    float* Vs   = Kt + 64 * KTS;        // [256][72]   Vs[tok][d]
    float* Ps   = Vs + 256 * VSS;       // [64][260]   scores/probs row-major
    float* Qs   = Ps + 64 * PSS;        // [64][68]    Qs[qi][d]
    float* rsum = Qs + 64 * QSS;        // [64]

    const int tid  = threadIdx.x;
    const int lane = tid & 31;
    const int warp = tid >> 5;
    const int warpM = warp >> 2;        // 0..1
    const int warpN = warp & 3;         // 0..3
    const int g = lane >> 2;            // 0..7
    const int t = lane & 3;             // 0..3

    const int b = blockIdx.x / HH;
    const int h = blockIdx.x % HH;
    const float* base = qkv + (size_t)b * TT * LDQKV;
    const float scale = 0.05103103630798288f;  // 384^-0.5 (full-embed quirk)

    // ---- Stage K (transposed, tf32) and V (tf32) ----
    {
        const int d4 = (tid & 15) * 4;
        for (int tok = tid >> 4; tok < TT; tok += 16) {
            const float* row = base + (size_t)tok * LDQKV + h * DD + d4;
            float4 kv = *(const float4*)(row);                 // K at offset 0
            Kt[(d4+0)*KTS + tok] = tf32_big(kv.x);
            Kt[(d4+1)*KTS + tok] = tf32_big(kv.y);
            Kt[(d4+2)*KTS + tok] = tf32_big(kv.z);
            Kt[(d4+3)*KTS + tok] = tf32_big(kv.w);
            float4 vv = *(const float4*)(row + 2*CC);          // V at offset 2C
            vv.x = tf32_big(vv.x); vv.y = tf32_big(vv.y);
            vv.z = tf32_big(vv.z); vv.w = tf32_big(vv.w);
            *(float4*)&Vs[tok*VSS + d4] = vv;
        }
    }

    for (int qt = 0; qt < 4; qt++) {
        __syncthreads();
        // ---- Stage Q tile (row-major, tf32) ----
        {
            const int d4 = (tid & 15) * 4;
            #pragma unroll
            for (int qi = tid >> 4; qi < 64; qi += 16) {
                float4 qv = *(const float4*)(base + (size_t)(qt*64 + qi) * LDQKV
                                             + CC + h * DD + d4);   // Q at offset C
                qv.x = tf32_big(qv.x); qv.y = tf32_big(qv.y);
                qv.z = tf32_big(qv.z); qv.w = tf32_big(qv.w);
                *(float4*)&Qs[qi*QSS + d4] = qv;
            }
        }
        __syncthreads();

        // ---- QK^T: S[64, 256] = Q @ K^T, skip warp-cols above diagonal ----
        if (warpN <= qt) {
            const int wm = warpM * 32;
            const int wn0 = warpN * 64;
            float acc[2][8][4];
            #pragma unroll
            for (int i = 0; i < 2; i++)
                #pragma unroll
                for (int j = 0; j < 8; j++)
                    #pragma unroll
                    for (int l = 0; l < 4; l++) acc[i][j][l] = 0.f;

            #pragma unroll
            for (int s = 0; s < 8; s++) {
                const int kc = s * 8 + t;
                uint32_t af[2][4], bf[8][2];
                #pragma unroll
                for (int mt = 0; mt < 2; mt++) {
                    const int r0 = (wm + mt * 16 + g) * QSS + kc;
                    af[mt][0] = __float_as_uint(Qs[r0]);
                    af[mt][1] = __float_as_uint(Qs[r0 + 8 * QSS]);
                    af[mt][2] = __float_as_uint(Qs[r0 + 4]);
                    af[mt][3] = __float_as_uint(Qs[r0 + 8 * QSS + 4]);
                }
                #pragma unroll
                for (int nt = 0; nt < 8; nt++) {
                    const int c0 = kc * KTS + wn0 + nt * 8 + g;
                    bf[nt][0] = __float_as_uint(Kt[c0]);
                    bf[nt][1] = __float_as_uint(Kt[c0 + 4 * KTS]);
                }
                #pragma unroll
                for (int mt = 0; mt < 2; mt++)
                    #pragma unroll
                    for (int nt = 0; nt < 8; nt++)
                        mma8(acc[mt][nt], af[mt], bf[nt]);
            }
            #pragma unroll
            for (int mt = 0; mt < 2; mt++)
                #pragma unroll
                for (int nt = 0; nt < 8; nt++) {
                    const int row = wm + mt * 16 + g;
                    const int col = wn0 + nt * 8 + 2 * t;
                    *(float2*)&Ps[row * PSS + col] =
                        make_float2(acc[mt][nt][0], acc[mt][nt][1]);
                    *(float2*)&Ps[(row + 8) * PSS + col] =
                        make_float2(acc[mt][nt][2], acc[mt][nt][3]);
                }
        }
        __syncthreads();

        // ---- causal softmax over rows of Ps; store tf32-rounded P ----
        {
            const int nj = (qt + 1) * 64;
            #pragma unroll
            for (int r = 0; r < 8; r++) {
                const int qi = warp * 8 + r;
                const int nv = qt * 64 + qi + 1;   // valid j in [0, nv)
                float m = -1e30f;
                for (int j = lane; j < nv; j += 32) m = fmaxf(m, Ps[qi*PSS + j]);
                #pragma unroll
                for (int o = 16; o; o >>= 1) m = fmaxf(m, __shfl_xor_sync(0xffffffffu, m, o));
                m *= scale;
                float ssum = 0.f;
                for (int j = lane; j < nj; j += 32) {
                    float p = (j < nv) ? __expf(Ps[qi*PSS + j] * scale - m) : 0.f;
                    Ps[qi*PSS + j] = tf32_big(p);
                    ssum += p;
                }
                #pragma unroll
                for (int o = 16; o; o >>= 1) ssum += __shfl_xor_sync(0xffffffffu, ssum, o);
                if (lane == 0) rsum[qi] = 1.f / ssum;
            }
        }
        __syncthreads();

        // ---- PV: O[64, 64] = P[64, nj] @ V[nj, 64] ----
        {
            const int wm = warpM * 32;
            const int wn = warpN * 16;
            const int KS = (qt + 1) * 8;    // k-steps (causal truncation)
            float acc[2][2][4];
            #pragma unroll
            for (int i = 0; i < 2; i++)
                #pragma unroll
                for (int j = 0; j < 2; j++)
                    #pragma unroll
                    for (int l = 0; l < 4; l++) acc[i][j][l] = 0.f;

            for (int s = 0; s < KS; s++) {
                const int kc = s * 8 + t;
                uint32_t af[2][4], bf[2][2];
                #pragma unroll
                for (int mt = 0; mt < 2; mt++) {
                    const int r0 = (wm + mt * 16 + g) * PSS + kc;
                    af[mt][0] = __float_as_uint(Ps[r0]);
                    af[mt][1] = __float_as_uint(Ps[r0 + 8 * PSS]);
                    af[mt][2] = __float_as_uint(Ps[r0 + 4]);
                    af[mt][3] = __float_as_uint(Ps[r0 + 8 * PSS + 4]);
                }
                #pragma unroll
                for (int nt = 0; nt < 2; nt++) {
                    const int c0 = kc * VSS + wn + nt * 8 + g;
                    bf[nt][0] = __float_as_uint(Vs[c0]);
                    bf[nt][1] = __float_as_uint(Vs[c0 + 4 * VSS]);
                }
                #pragma unroll
                for (int mt = 0; mt < 2; mt++)
                    #pragma unroll
                    for (int nt = 0; nt < 2; nt++)
                        mma8(acc[mt][nt], af[mt], bf[nt]);
            }
            #pragma unroll
            for (int mt = 0; mt < 2; mt++)
                #pragma unroll
                for (int nt = 0; nt < 2; nt++) {
                    const int row = wm + mt * 16 + g;
                    const int col = wn + nt * 8 + 2 * t;
                    const float s0 = rsum[row], s1 = rsum[row + 8];
                    size_t r0 = ((size_t)b * TT + qt*64 + row) * CC + h * DD + col;
                    *(float2*)&att[r0] =
                        make_float2(acc[mt][nt][0] * s0, acc[mt][nt][1] * s0);
                    *(float2*)&att[r0 + (size_t)8 * CC] =
                        make_float2(acc[mt][nt][2] * s1, acc[mt][nt][3] * s1);
                }
        }
    }
}

// ============================================================
extern "C" void kernel_launch(void* const* d_in, const int* in_sizes, int n_in,
                              void* d_out, int out_size)
{
    const float* X     = (const float*)d_in[0];
    const float* Wqkv  = (const float*)d_in[1];
    const float* Wproj = (const float*)d_in[2];
    float* out = (float*)d_out;

    void *p0, *p1;
    cudaGetSymbolAddress(&p0, g_qkv);
    cudaGetSymbolAddress(&p1, g_att);
    float* qkv = (float*)p0;
    float* att = (float*)p1;

    cudaFuncSetAttribute(gemm_tf32x3, cudaFuncAttributeMaxDynamicSharedMemorySize,
                         GEMM_SMEM_BYTES);
    cudaFuncSetAttribute(attn_kernel, cudaFuncAttributeMaxDynamicSharedMemorySize,
                         ATTN_SMEM_BYTES);

    // 1) qkv = X @ Wqkv     [32768,1152] = [32768,384]@[384,1152]
    dim3 g1(3 * CC / 128, BB * TT / 128);       // (9, 256)
    gemm_tf32x3<<<g1, 512, GEMM_SMEM_BYTES>>>(X, Wqkv, qkv, BB * TT, 3 * CC, CC);

    // 2) fused causal attention -> att [32768,384]
    attn_kernel<<<BB * HH, 256, ATTN_SMEM_BYTES>>>(qkv, att);

    // 3) out = att @ Wproj  [32768,384] = [32768,384]@[384,384]
    dim3 g3(CC / 128, BB * TT / 128);           // (3, 256)
    gemm_tf32x3<<<g3, 512, GEMM_SMEM_BYTES>>>(att, Wproj, out, BB * TT, CC, CC);
}

// round 4
// speedup vs baseline: 1.6869x; 1.1444x over previous
#include <cuda_runtime.h>
#include <cstdint>
#include <cstddef>

#define BB  128
#define TT  256
#define CC  384
#define HH  6
#define DD  64
#define LDQKV (3*CC)   // 1152

typedef unsigned long long u64;

// Scratch (device globals: allocation-free per harness rules)
__device__ float g_qkv[(size_t)BB * TT * 3 * CC];  // [32768][1152]
__device__ float g_att[(size_t)BB * TT * CC];      // [32768][384]

// ---------- tf32 helpers ----------
__device__ __forceinline__ float tf32_big(float f) {
    uint32_t r; asm("cvt.rna.tf32.f32 %0, %1;" : "=r"(r) : "f"(f));
    return __uint_as_float(r);
}
__device__ __forceinline__ void mma8(float* c, const uint32_t* a, const uint32_t* b) {
    asm volatile("mma.sync.aligned.m16n8k8.row.col.f32.tf32.tf32.f32 "
        "{%0,%1,%2,%3}, {%4,%5,%6,%7}, {%8,%9}, {%0,%1,%2,%3};"
        : "+f"(c[0]), "+f"(c[1]), "+f"(c[2]), "+f"(c[3])
        : "r"(a[0]), "r"(a[1]), "r"(a[2]), "r"(a[3]), "r"(b[0]), "r"(b[1]));
}

// ============================================================
// GEMM via 2xTF32 tensor-core mma: C[M,N]=A[M,K]@B[K,N] fp32.
// A split big+small (fragment-major smem, LDS.128 per fragment);
// B rounded once (rna), [k][136] padded layout, conflict-free.
// Block 128x128, BK=32, 512 threads (16 warps, warp tile 32x32).
// ============================================================
#define AFS 160                              // floats per (s, mchunk) block
#define AFRAG_FLOATS (4*8*AFS)               // 5120 per copy
#define BSTRIDE 136
#define GEMM_SMEM_FLOATS (2*AFRAG_FLOATS + 32*BSTRIDE)   // 14592
#define GEMM_SMEM_BYTES  (GEMM_SMEM_FLOATS * 4)          // 58368

__global__ __launch_bounds__(512, 1)
void gemm_tf32x2(const float* __restrict__ A, const float* __restrict__ B,
                 float* __restrict__ Cm, int M, int N, int K)
{
    extern __shared__ __align__(16) float sm[];
    float* Ab = sm;                        // fragment-major big
    float* Al = Ab + AFRAG_FLOATS;         // fragment-major small
    float* Bb = Al + AFRAG_FLOATS;         // [32][136] tf32-rounded

    const int tid  = threadIdx.x;
    const int lane = tid & 31;
    const int warp = tid >> 5;
    const int bm = blockIdx.y * 128;
    const int bn = blockIdx.x * 128;
    const int warpM = warp >> 2;           // 0..3
    const int wn = (warp & 3) * 32;

    const int g = lane >> 2;               // 0..7
    const int t = lane & 3;                // 0..3

    // staging assignments
    const int arow = tid >> 2;             // 0..127
    const int s4   = tid & 3;              // k-chunk 0..3
    const int amc  = arow >> 4;            // mchunk
    const int ag   = arow & 7;
    const int arbit = (arow >> 3) & 1;
    const int abase = (s4 * 8 + amc) * AFS + ag * 20;

    const int bk   = tid >> 4;             // 0..31
    const int bn0  = (tid & 15) * 8;       // 0..120

    const float* Ap = A + (size_t)(bm + arow) * K + s4 * 8;
    const float* Bp = B + (size_t)bk * N + bn + bn0;

    float acc[2][4][4];
    #pragma unroll
    for (int i = 0; i < 2; i++)
        #pragma unroll
        for (int j = 0; j < 4; j++)
            #pragma unroll
            for (int l = 0; l < 4; l++) acc[i][j][l] = 0.f;

    const int KT = K >> 5;
    float4 ra0 = *(const float4*)(Ap);
    float4 ra1 = *(const float4*)(Ap + 4);
    float4 rb0 = *(const float4*)(Bp);
    float4 rb1 = *(const float4*)(Bp + 4);

    for (int kt = 0; kt < KT; kt++) {
        __syncthreads();
        // ---- stage A (split, fragment-major, conflict-free STS) ----
        {
            float av[8];
            av[0]=ra0.x; av[1]=ra0.y; av[2]=ra0.z; av[3]=ra0.w;
            av[4]=ra1.x; av[5]=ra1.y; av[6]=ra1.z; av[7]=ra1.w;
            #pragma unroll
            for (int j = 0; j < 8; j++) {
                float big = tf32_big(av[j]);
                const int reg = arbit + (j >> 2) * 2;
                const int pos = abase + (((j & 3) ^ s4) << 2) + (reg ^ s4);
                Ab[pos] = big;
                Al[pos] = av[j] - big;
            }
            // ---- stage B (rounded once) ----
            float4 hb;
            hb.x = tf32_big(rb0.x); hb.y = tf32_big(rb0.y);
            hb.z = tf32_big(rb0.z); hb.w = tf32_big(rb0.w);
            *(float4*)&Bb[bk * BSTRIDE + bn0] = hb;
            hb.x = tf32_big(rb1.x); hb.y = tf32_big(rb1.y);
            hb.z = tf32_big(rb1.z); hb.w = tf32_big(rb1.w);
            *(float4*)&Bb[bk * BSTRIDE + bn0 + 4] = hb;
        }
        __syncthreads();

        if (kt + 1 < KT) {   // prefetch next gmem tile
            const float* Ap2 = Ap + (kt + 1) * 32;
            ra0 = *(const float4*)(Ap2);
            ra1 = *(const float4*)(Ap2 + 4);
            const float* Bp2 = Bp + (size_t)(kt + 1) * 32 * N;
            rb0 = *(const float4*)(Bp2);
            rb1 = *(const float4*)(Bp2 + 4);
        }

        #pragma unroll
        for (int s = 0; s < 4; s++) {
            // A fragments: one LDS.128 per (mt, copy)
            uint32_t afb[2][4], afl[2][4];
            #pragma unroll
            for (int mt = 0; mt < 2; mt++) {
                const int mc = warpM * 2 + mt;
                const int base = (s * 8 + mc) * AFS + g * 20 + ((t ^ s) << 2);
                float tb[4], tl[4];
                *(float4*)tb = *(const float4*)&Ab[base];
                *(float4*)tl = *(const float4*)&Al[base];
                #pragma unroll
                for (int r = 0; r < 4; r++) {
                    afb[mt][r] = __float_as_uint(tb[r ^ s]);
                    afl[mt][r] = __float_as_uint(tl[r ^ s]);
                }
            }
            // B fragments: conflict-free LDS.32
            const int kc = s * 8 + t;
            uint32_t bf[4][2];
            #pragma unroll
            for (int nt = 0; nt < 4; nt++) {
                const int c0 = kc * BSTRIDE + wn + nt * 8 + g;
                bf[nt][0] = __float_as_uint(Bb[c0]);
                bf[nt][1] = __float_as_uint(Bb[c0 + 4 * BSTRIDE]);
            }
            #pragma unroll
            for (int mt = 0; mt < 2; mt++)
                #pragma unroll
                for (int nt = 0; nt < 4; nt++) {
                    mma8(acc[mt][nt], afl[mt], bf[nt]);   // small * B
                    mma8(acc[mt][nt], afb[mt], bf[nt]);   // big * B
                }
        }
    }

    // epilogue
    const int wm = warpM * 32;
    #pragma unroll
    for (int mt = 0; mt < 2; mt++)
        #pragma unroll
        for (int nt = 0; nt < 4; nt++) {
            const int row = bm + wm + mt * 16 + g;
            const int col = bn + wn + nt * 8 + 2 * t;
            *(float2*)&Cm[(size_t)row * N + col] =
                make_float2(acc[mt][nt][0], acc[mt][nt][1]);
            *(float2*)&Cm[(size_t)(row + 8) * N + col] =
                make_float2(acc[mt][nt][2], acc[mt][nt][3]);
        }
}

// ============================================================
// Tensor-core fused causal attention per (b, h).  (unchanged R3)
// ============================================================
#define KTS 264
#define VSS 72
#define PSS 260
#define QSS 68
#define ATTN_SMEM_FLOATS (64*KTS + 256*VSS + 64*PSS + 64*QSS + 64)  // 56384
#define ATTN_SMEM_BYTES  (ATTN_SMEM_FLOATS * 4)                      // 225536

__global__ __launch_bounds__(256, 1)
void attn_kernel(const float* __restrict__ qkv, float* __restrict__ att)
{
    extern __shared__ __align__(16) float sm[];
    float* Kt   = sm;                   // [64][264]   Kt[d][tok]
    float* Vs   = Kt + 64 * KTS;        // [256][72]   Vs[tok][d]
    float* Ps   = Vs + 256 * VSS;       // [64][260]   scores/probs row-major
    float* Qs   = Ps + 64 * PSS;        // [64][68]    Qs[qi][d]
    float* rsum = Qs + 64 * QSS;        // [64]

    const int tid  = threadIdx.x;
    const int lane = tid & 31;
    const int warp = tid >> 5;
    const int warpM = warp >> 2;        // 0..1
    const int warpN = warp & 3;         // 0..3
    const int g = lane >> 2;            // 0..7
    const int t = lane & 3;             // 0..3

    const int b = blockIdx.x / HH;
    const int h = blockIdx.x % HH;
    const float* base = qkv + (size_t)b * TT * LDQKV;
    const float scale = 0.05103103630798288f;  // 384^-0.5 (full-embed quirk)

    // ---- Stage K (transposed, tf32) and V (tf32) ----
    {
        const int d4 = (tid & 15) * 4;
        for (int tok = tid >> 4; tok < TT; tok += 16) {
            const float* row = base + (size_t)tok * LDQKV + h * DD + d4;
            float4 kv = *(const float4*)(row);                 // K at offset 0
            Kt[(d4+0)*KTS + tok] = tf32_big(kv.x);
            Kt[(d4+1)*KTS + tok] = tf32_big(kv.y);
            Kt[(d4+2)*KTS + tok] = tf32_big(kv.z);
            Kt[(d4+3)*KTS + tok] = tf32_big(kv.w);
            float4 vv = *(const float4*)(row + 2*CC);          // V at offset 2C
            vv.x = tf32_big(vv.x); vv.y = tf32_big(vv.y);
            vv.z = tf32_big(vv.z); vv.w = tf32_big(vv.w);
            *(float4*)&Vs[tok*VSS + d4] = vv;
        }
    }

    for (int qt = 0; qt < 4; qt++) {
        __syncthreads();
        // ---- Stage Q tile (row-major, tf32) ----
        {
            const int d4 = (tid & 15) * 4;
            #pragma unroll
            for (int qi = tid >> 4; qi < 64; qi += 16) {
                float4 qv = *(const float4*)(base + (size_t)(qt*64 + qi) * LDQKV
                                             + CC + h * DD + d4);   // Q at offset C
                qv.x = tf32_big(qv.x); qv.y = tf32_big(qv.y);
                qv.z = tf32_big(qv.z); qv.w = tf32_big(qv.w);
                *(float4*)&Qs[qi*QSS + d4] = qv;
            }
        }
        __syncthreads();

        // ---- QK^T: S[64, 256] = Q @ K^T, skip warp-cols above diagonal ----
        if (warpN <= qt) {
            const int wm = warpM * 32;
            const int wn0 = warpN * 64;
            float acc[2][8][4];
            #pragma unroll
            for (int i = 0; i < 2; i++)
                #pragma unroll
                for (int j = 0; j < 8; j++)
                    #pragma unroll
                    for (int l = 0; l < 4; l++) acc[i][j][l] = 0.f;

            #pragma unroll
            for (int s = 0; s < 8; s++) {
                const int kc = s * 8 + t;
                uint32_t af[2][4], bf[8][2];
                #pragma unroll
                for (int mt = 0; mt < 2; mt++) {
                    const int r0 = (wm + mt * 16 + g) * QSS + kc;
                    af[mt][0] = __float_as_uint(Qs[r0]);
                    af[mt][1] = __float_as_uint(Qs[r0 + 8 * QSS]);
                    af[mt][2] = __float_as_uint(Qs[r0 + 4]);
                    af[mt][3] = __float_as_uint(Qs[r0 + 8 * QSS + 4]);
                }
                #pragma unroll
                for (int nt = 0; nt < 8; nt++) {
                    const int c0 = kc * KTS + wn0 + nt * 8 + g;
                    bf[nt][0] = __float_as_uint(Kt[c0]);
                    bf[nt][1] = __float_as_uint(Kt[c0 + 4 * KTS]);
                }
                #pragma unroll
                for (int mt = 0; mt < 2; mt++)
                    #pragma unroll
                    for (int nt = 0; nt < 8; nt++)
                        mma8(acc[mt][nt], af[mt], bf[nt]);
            }
            #pragma unroll
            for (int mt = 0; mt < 2; mt++)
                #pragma unroll
                for (int nt = 0; nt < 8; nt++) {
                    const int row = wm + mt * 16 + g;
                    const int col = wn0 + nt * 8 + 2 * t;
                    *(float2*)&Ps[row * PSS + col] =
                        make_float2(acc[mt][nt][0], acc[mt][nt][1]);
                    *(float2*)&Ps[(row + 8) * PSS + col] =
                        make_float2(acc[mt][nt][2], acc[mt][nt][3]);
                }
        }
        __syncthreads();

        // ---- causal softmax over rows of Ps; store tf32-rounded P ----
        {
            const int nj = (qt + 1) * 64;
            #pragma unroll
            for (int r = 0; r < 8; r++) {
                const int qi = warp * 8 + r;
                const int nv = qt * 64 + qi + 1;   // valid j in [0, nv)
                float m = -1e30f;
                for (int j = lane; j < nv; j += 32) m = fmaxf(m, Ps[qi*PSS + j]);
                #pragma unroll
                for (int o = 16; o; o >>= 1) m = fmaxf(m, __shfl_xor_sync(0xffffffffu, m, o));
                m *= scale;
                float ssum = 0.f;
                for (int j = lane; j < nj; j += 32) {
                    float p = (j < nv) ? __expf(Ps[qi*PSS + j] * scale - m) : 0.f;
                    Ps[qi*PSS + j] = tf32_big(p);
                    ssum += p;
                }
                #pragma unroll
                for (int o = 16; o; o >>= 1) ssum += __shfl_xor_sync(0xffffffffu, ssum, o);
                if (lane == 0) rsum[qi] = 1.f / ssum;
            }
        }
        __syncthreads();

        // ---- PV: O[64, 64] = P[64, nj] @ V[nj, 64] ----
        {
            const int wm = warpM * 32;
            const int wn = warpN * 16;
            const int KS = (qt + 1) * 8;    // k-steps (causal truncation)
            float acc[2][2][4];
            #pragma unroll
            for (int i = 0; i < 2; i++)
                #pragma unroll
                for (int j = 0; j < 2; j++)
                    #pragma unroll
                    for (int l = 0; l < 4; l++) acc[i][j][l] = 0.f;

            for (int s = 0; s < KS; s++) {
                const int kc = s * 8 + t;
                uint32_t af[2][4], bf[2][2];
                #pragma unroll
                for (int mt = 0; mt < 2; mt++) {
                    const int r0 = (wm + mt * 16 + g) * PSS + kc;
                    af[mt][0] = __float_as_uint(Ps[r0]);
                    af[mt][1] = __float_as_uint(Ps[r0 + 8 * PSS]);
                    af[mt][2] = __float_as_uint(Ps[r0 + 4]);
                    af[mt][3] = __float_as_uint(Ps[r0 + 8 * PSS + 4]);
                }
                #pragma unroll
                for (int nt = 0; nt < 2; nt++) {
                    const int c0 = kc * VSS + wn + nt * 8 + g;
                    bf[nt][0] = __float_as_uint(Vs[c0]);
                    bf[nt][1] = __float_as_uint(Vs[c0 + 4 * VSS]);
                }
                #pragma unroll
                for (int mt = 0; mt < 2; mt++)
                    #pragma unroll
                    for (int nt = 0; nt < 2; nt++)
                        mma8(acc[mt][nt], af[mt], bf[nt]);
            }
            #pragma unroll
            for (int mt = 0; mt < 2; mt++)
                #pragma unroll
                for (int nt = 0; nt < 2; nt++) {
                    const int row = wm + mt * 16 + g;
                    const int col = wn + nt * 8 + 2 * t;
                    const float s0 = rsum[row], s1 = rsum[row + 8];
                    size_t r0 = ((size_t)b * TT + qt*64 + row) * CC + h * DD + col;
                    *(float2*)&att[r0] =
                        make_float2(acc[mt][nt][0] * s0, acc[mt][nt][1] * s0);
                    *(float2*)&att[r0 + (size_t)8 * CC] =
                        make_float2(acc[mt][nt][2] * s1, acc[mt][nt][3] * s1);
                }
        }
    }
}

// ============================================================
extern "C" void kernel_launch(void* const* d_in, const int* in_sizes, int n_in,
                              void* d_out, int out_size)
{
    const float* X     = (const float*)d_in[0];
    const float* Wqkv  = (const float*)d_in[1];
    const float* Wproj = (const float*)d_in[2];
    float* out = (float*)d_out;

    void *p0, *p1;
    cudaGetSymbolAddress(&p0, g_qkv);
    cudaGetSymbolAddress(&p1, g_att);
    float* qkv = (float*)p0;
    float* att = (float*)p1;

    cudaFuncSetAttribute(gemm_tf32x2, cudaFuncAttributeMaxDynamicSharedMemorySize,
                         GEMM_SMEM_BYTES);
    cudaFuncSetAttribute(attn_kernel, cudaFuncAttributeMaxDynamicSharedMemorySize,
                         ATTN_SMEM_BYTES);

    // 1) qkv = X @ Wqkv     [32768,1152] = [32768,384]@[384,1152]
    dim3 g1(3 * CC / 128, BB * TT / 128);       // (9, 256)
    gemm_tf32x2<<<g1, 512, GEMM_SMEM_BYTES>>>(X, Wqkv, qkv, BB * TT, 3 * CC, CC);

    // 2) fused causal attention -> att [32768,384]
    attn_kernel<<<BB * HH, 256, ATTN_SMEM_BYTES>>>(qkv, att);

    // 3) out = att @ Wproj  [32768,384] = [32768,384]@[384,384]
    dim3 g3(CC / 128, BB * TT / 128);           // (3, 256)
    gemm_tf32x2<<<g3, 512, GEMM_SMEM_BYTES>>>(att, Wproj, out, BB * TT, CC, CC);
}

// round 6
// speedup vs baseline: 1.8383x; 1.0897x over previous
#include <cuda_runtime.h>
#include <cstdint>
#include <cstddef>

#define BB  128
#define TT  256
#define CC  384
#define HH  6
#define DD  64
#define LDQKV (3*CC)   // 1152

typedef unsigned long long u64;

// Scratch (device globals: allocation-free per harness rules)
__device__ float g_qkv[(size_t)BB * TT * 3 * CC];  // [32768][1152]
__device__ float g_att[(size_t)BB * TT * CC];      // [32768][384]

// ---------- tf32 helpers ----------
__device__ __forceinline__ float tf32_big(float f) {
    uint32_t r; asm("cvt.rna.tf32.f32 %0, %1;" : "=r"(r) : "f"(f));
    return __uint_as_float(r);
}
__device__ __forceinline__ void mma8(float* c, const uint32_t* a, const uint32_t* b) {
    asm volatile("mma.sync.aligned.m16n8k8.row.col.f32.tf32.tf32.f32 "
        "{%0,%1,%2,%3}, {%4,%5,%6,%7}, {%8,%9}, {%0,%1,%2,%3};"
        : "+f"(c[0]), "+f"(c[1]), "+f"(c[2]), "+f"(c[3])
        : "r"(a[0]), "r"(a[1]), "r"(a[2]), "r"(a[3]), "r"(b[0]), "r"(b[1]));
}

// ============================================================
// GEMM via 1xTF32 tensor-core mma: C[M,N]=A[M,K]@B[K,N] fp32.
// A and B rna-rounded once at smem staging. R3-verified
// conflict-free layouts: A [128][36], B [32][136].
// Block 128x128, BK=32, 512 threads (16 warps, warp tile 32x32).
// Requires M%128==0, N%128==0, K%32==0.
// ============================================================
#define ASTRIDE 36
#define BSTRIDE 136
#define GEMM_SMEM_FLOATS (128*ASTRIDE + 32*BSTRIDE)   // 8960
#define GEMM_SMEM_BYTES  (GEMM_SMEM_FLOATS * 4)       // 35840

__global__ __launch_bounds__(512, 2)
void gemm_tf32x1(const float* __restrict__ A, const float* __restrict__ B,
                 float* __restrict__ Cm, int M, int N, int K)
{
    extern __shared__ __align__(16) float sm[];
    float* Ab = sm;                       // [128][36]  tf32-rounded A
    float* Bb = Ab + 128 * ASTRIDE;       // [32][136]  tf32-rounded B

    const int tid  = threadIdx.x;
    const int lane = tid & 31;
    const int warp = tid >> 5;
    const int bm = blockIdx.y * 128;
    const int bn = blockIdx.x * 128;
    const int wm = (warp >> 2) * 32;
    const int wn = (warp & 3) * 32;

    const int arow = tid >> 2;            // 0..127
    const int acol = (tid & 3) * 8;       // 0,8,16,24
    const int bk   = tid >> 4;            // 0..31
    const int bn0  = (tid & 15) * 8;      // 0..120

    const float* Ap = A + (size_t)(bm + arow) * K + acol;
    const float* Bp = B + (size_t)bk * N + bn + bn0;

    float acc[2][4][4];
    #pragma unroll
    for (int i = 0; i < 2; i++)
        #pragma unroll
        for (int j = 0; j < 4; j++)
            #pragma unroll
            for (int l = 0; l < 4; l++) acc[i][j][l] = 0.f;

    const int KT = K >> 5;
    float4 ra0 = *(const float4*)(Ap);
    float4 ra1 = *(const float4*)(Ap + 4);
    float4 rb0 = *(const float4*)(Bp);
    float4 rb1 = *(const float4*)(Bp + 4);

    const int g = lane >> 2;   // 0..7
    const int t = lane & 3;    // 0..3

    for (int kt = 0; kt < KT; kt++) {
        __syncthreads();
        {
            float4 hb;
            hb.x = tf32_big(ra0.x); hb.y = tf32_big(ra0.y);
            hb.z = tf32_big(ra0.z); hb.w = tf32_big(ra0.w);
            *(float4*)&Ab[arow * ASTRIDE + acol] = hb;
            hb.x = tf32_big(ra1.x); hb.y = tf32_big(ra1.y);
            hb.z = tf32_big(ra1.z); hb.w = tf32_big(ra1.w);
            *(float4*)&Ab[arow * ASTRIDE + acol + 4] = hb;
            hb.x = tf32_big(rb0.x); hb.y = tf32_big(rb0.y);
            hb.z = tf32_big(rb0.z); hb.w = tf32_big(rb0.w);
            *(float4*)&Bb[bk * BSTRIDE + bn0] = hb;
            hb.x = tf32_big(rb1.x); hb.y = tf32_big(rb1.y);
            hb.z = tf32_big(rb1.z); hb.w = tf32_big(rb1.w);
            *(float4*)&Bb[bk * BSTRIDE + bn0 + 4] = hb;
        }
        __syncthreads();

        if (kt + 1 < KT) {   // prefetch next gmem tile
            const float* Ap2 = Ap + (kt + 1) * 32;
            ra0 = *(const float4*)(Ap2);
            ra1 = *(const float4*)(Ap2 + 4);
            const float* Bp2 = Bp + (size_t)(kt + 1) * 32 * N;
            rb0 = *(const float4*)(Bp2);
            rb1 = *(const float4*)(Bp2 + 4);
        }

        #pragma unroll
        for (int s = 0; s < 4; s++) {
            const int kc = s * 8 + t;
            uint32_t af[2][4], bf[4][2];
            #pragma unroll
            for (int mt = 0; mt < 2; mt++) {
                const int r0 = (wm + mt * 16 + g) * ASTRIDE + kc;
                af[mt][0] = __float_as_uint(Ab[r0]);
                af[mt][1] = __float_as_uint(Ab[r0 + 8 * ASTRIDE]);
                af[mt][2] = __float_as_uint(Ab[r0 + 4]);
                af[mt][3] = __float_as_uint(Ab[r0 + 8 * ASTRIDE + 4]);
            }
            #pragma unroll
            for (int nt = 0; nt < 4; nt++) {
                const int c0 = kc * BSTRIDE + wn + nt * 8 + g;
                bf[nt][0] = __float_as_uint(Bb[c0]);
                bf[nt][1] = __float_as_uint(Bb[c0 + 4 * BSTRIDE]);
            }
            #pragma unroll
            for (int mt = 0; mt < 2; mt++)
                #pragma unroll
                for (int nt = 0; nt < 4; nt++)
                    mma8(acc[mt][nt], af[mt], bf[nt]);
        }
    }

    // epilogue
    #pragma unroll
    for (int mt = 0; mt < 2; mt++)
        #pragma unroll
        for (int nt = 0; nt < 4; nt++) {
            const int row = bm + wm + mt * 16 + g;
            const int col = bn + wn + nt * 8 + 2 * t;
            *(float2*)&Cm[(size_t)row * N + col] =
                make_float2(acc[mt][nt][0], acc[mt][nt][1]);
            *(float2*)&Cm[(size_t)(row + 8) * N + col] =
                make_float2(acc[mt][nt][2], acc[mt][nt][3]);
        }
}

// ============================================================
// Tensor-core fused causal attention per (b, h).  (unchanged R4)
// ============================================================
#define KTS 264
#define VSS 72
#define PSS 260
#define QSS 68
#define ATTN_SMEM_FLOATS (64*KTS + 256*VSS + 64*PSS + 64*QSS + 64)  // 56384
#define ATTN_SMEM_BYTES  (ATTN_SMEM_FLOATS * 4)                      // 225536

__global__ __launch_bounds__(256, 1)
void attn_kernel(const float* __restrict__ qkv, float* __restrict__ att)
{
    extern __shared__ __align__(16) float smf[];
    float* Kt   = smf;                  // [64][264]   Kt[d][tok]
    float* Vs   = Kt + 64 * KTS;        // [256][72]   Vs[tok][d]
    float* Ps   = Vs + 256 * VSS;       // [64][260]   scores/probs row-major
    float* Qs   = Ps + 64 * PSS;        // [64][68]    Qs[qi][d]
    float* rsum = Qs + 64 * QSS;        // [64]

    const int tid  = threadIdx.x;
    const int lane = tid & 31;
    const int warp = tid >> 5;
    const int warpM = warp >> 2;        // 0..1
    const int warpN = warp & 3;         // 0..3
    const int g = lane >> 2;            // 0..7
    const int t = lane & 3;             // 0..3

    const int b = blockIdx.x / HH;
    const int h = blockIdx.x % HH;
    const float* base = qkv + (size_t)b * TT * LDQKV;
    const float scale = 0.05103103630798288f;  // 384^-0.5 (full-embed quirk)

    // ---- Stage K (transposed, tf32) and V (tf32) ----
    {
        const int d4 = (tid & 15) * 4;
        for (int tok = tid >> 4; tok < TT; tok += 16) {
            const float* row = base + (size_t)tok * LDQKV + h * DD + d4;
            float4 kv = *(const float4*)(row);                 // K at offset 0
            Kt[(d4+0)*KTS + tok] = tf32_big(kv.x);
            Kt[(d4+1)*KTS + tok] = tf32_big(kv.y);
            Kt[(d4+2)*KTS + tok] = tf32_big(kv.z);
            Kt[(d4+3)*KTS + tok] = tf32_big(kv.w);
            float4 vv = *(const float4*)(row + 2*CC);          // V at offset 2C
            vv.x = tf32_big(vv.x); vv.y = tf32_big(vv.y);
            vv.z = tf32_big(vv.z); vv.w = tf32_big(vv.w);
            *(float4*)&Vs[tok*VSS + d4] = vv;
        }
    }

    for (int qt = 0; qt < 4; qt++) {
        __syncthreads();
        // ---- Stage Q tile (row-major, tf32) ----
        {
            const int d4 = (tid & 15) * 4;
            #pragma unroll
            for (int qi = tid >> 4; qi < 64; qi += 16) {
                float4 qv = *(const float4*)(base + (size_t)(qt*64 + qi) * LDQKV
                                             + CC + h * DD + d4);   // Q at offset C
                qv.x = tf32_big(qv.x); qv.y = tf32_big(qv.y);
                qv.z = tf32_big(qv.z); qv.w = tf32_big(qv.w);
                *(float4*)&Qs[qi*QSS + d4] = qv;
            }
        }
        __syncthreads();

        // ---- QK^T: S[64, 256] = Q @ K^T, skip warp-cols above diagonal ----
        if (warpN <= qt) {
            const int wm = warpM * 32;
            const int wn0 = warpN * 64;
            float acc[2][8][4];
            #pragma unroll
            for (int i = 0; i < 2; i++)
                #pragma unroll
                for (int j = 0; j < 8; j++)
                    #pragma unroll
                    for (int l = 0; l < 4; l++) acc[i][j][l] = 0.f;

            #pragma unroll
            for (int s = 0; s < 8; s++) {
                const int kc = s * 8 + t;
                uint32_t af[2][4], bf[8][2];
                #pragma unroll
                for (int mt = 0; mt < 2; mt++) {
                    const int r0 = (wm + mt * 16 + g) * QSS + kc;
                    af[mt][0] = __float_as_uint(Qs[r0]);
                    af[mt][1] = __float_as_uint(Qs[r0 + 8 * QSS]);
                    af[mt][2] = __float_as_uint(Qs[r0 + 4]);
                    af[mt][3] = __float_as_uint(Qs[r0 + 8 * QSS + 4]);
                }
                #pragma unroll
                for (int nt = 0; nt < 8; nt++) {
                    const int c0 = kc * KTS + wn0 + nt * 8 + g;
                    bf[nt][0] = __float_as_uint(Kt[c0]);
                    bf[nt][1] = __float_as_uint(Kt[c0 + 4 * KTS]);
                }
                #pragma unroll
                for (int mt = 0; mt < 2; mt++)
                    #pragma unroll
                    for (int nt = 0; nt < 8; nt++)
                        mma8(acc[mt][nt], af[mt], bf[nt]);
            }
            #pragma unroll
            for (int mt = 0; mt < 2; mt++)
                #pragma unroll
                for (int nt = 0; nt < 8; nt++) {
                    const int row = wm + mt * 16 + g;
                    const int col = wn0 + nt * 8 + 2 * t;
                    *(float2*)&Ps[row * PSS + col] =
                        make_float2(acc[mt][nt][0], acc[mt][nt][1]);
                    *(float2*)&Ps[(row + 8) * PSS + col] =
                        make_float2(acc[mt][nt][2], acc[mt][nt][3]);
                }
        }
        __syncthreads();

        // ---- causal softmax over rows of Ps; store tf32-rounded P ----
        {
            const int nj = (qt + 1) * 64;
            #pragma unroll
            for (int rr = 0; rr < 8; rr++) {
                const int qi = warp * 8 + rr;
                const int nv = qt * 64 + qi + 1;   // valid j in [0, nv)
                float m = -1e30f;
                for (int j = lane; j < nv; j += 32) m = fmaxf(m, Ps[qi*PSS + j]);
                #pragma unroll
                for (int o = 16; o; o >>= 1) m = fmaxf(m, __shfl_xor_sync(0xffffffffu, m, o));
                m *= scale;
                float ssum = 0.f;
                for (int j = lane; j < nj; j += 32) {
                    float p = (j < nv) ? __expf(Ps[qi*PSS + j] * scale - m) : 0.f;
                    Ps[qi*PSS + j] = tf32_big(p);
                    ssum += p;
                }
                #pragma unroll
                for (int o = 16; o; o >>= 1) ssum += __shfl_xor_sync(0xffffffffu, ssum, o);
                if (lane == 0) rsum[qi] = 1.f / ssum;
            }
        }
        __syncthreads();

        // ---- PV: O[64, 64] = P[64, nj] @ V[nj, 64] ----
        {
            const int wm = warpM * 32;
            const int wn = warpN * 16;
            const int KS = (qt + 1) * 8;    // k-steps (causal truncation)
            float acc[2][2][4];
            #pragma unroll
            for (int i = 0; i < 2; i++)
                #pragma unroll
                for (int j = 0; j < 2; j++)
                    #pragma unroll
                    for (int l = 0; l < 4; l++) acc[i][j][l] = 0.f;

            for (int s = 0; s < KS; s++) {
                const int kc = s * 8 + t;
                uint32_t af[2][4], bf[2][2];
                #pragma unroll
                for (int mt = 0; mt < 2; mt++) {
                    const int r0 = (wm + mt * 16 + g) * PSS + kc;
                    af[mt][0] = __float_as_uint(Ps[r0]);
                    af[mt][1] = __float_as_uint(Ps[r0 + 8 * PSS]);
                    af[mt][2] = __float_as_uint(Ps[r0 + 4]);
                    af[mt][3] = __float_as_uint(Ps[r0 + 8 * PSS + 4]);
                }
                #pragma unroll
                for (int nt = 0; nt < 2; nt++) {
                    const int c0 = kc * VSS + wn + nt * 8 + g;
                    bf[nt][0] = __float_as_uint(Vs[c0]);
                    bf[nt][1] = __float_as_uint(Vs[c0 + 4 * VSS]);
                }
                #pragma unroll
                for (int mt = 0; mt < 2; mt++)
                    #pragma unroll
                    for (int nt = 0; nt < 2; nt++)
                        mma8(acc[mt][nt], af[mt], bf[nt]);
            }
            #pragma unroll
            for (int mt = 0; mt < 2; mt++)
                #pragma unroll
                for (int nt = 0; nt < 2; nt++) {
                    const int row = wm + mt * 16 + g;
                    const int col = wn + nt * 8 + 2 * t;
                    const float s0 = rsum[row], s1 = rsum[row + 8];
                    size_t r0 = ((size_t)b * TT + qt*64 + row) * CC + h * DD + col;
                    *(float2*)&att[r0] =
                        make_float2(acc[mt][nt][0] * s0, acc[mt][nt][1] * s0);
                    *(float2*)&att[r0 + (size_t)8 * CC] =
                        make_float2(acc[mt][nt][2] * s1, acc[mt][nt][3] * s1);
                }
        }
    }
}

// ============================================================
extern "C" void kernel_launch(void* const* d_in, const int* in_sizes, int n_in,
                              void* d_out, int out_size)
{
    const float* X     = (const float*)d_in[0];
    const float* Wqkv  = (const float*)d_in[1];
    const float* Wproj = (const float*)d_in[2];
    float* out = (float*)d_out;

    void *p0, *p1;
    cudaGetSymbolAddress(&p0, g_qkv);
    cudaGetSymbolAddress(&p1, g_att);
    float* qkv = (float*)p0;
    float* att = (float*)p1;

    cudaFuncSetAttribute(gemm_tf32x1, cudaFuncAttributeMaxDynamicSharedMemorySize,
                         GEMM_SMEM_BYTES);
    cudaFuncSetAttribute(attn_kernel, cudaFuncAttributeMaxDynamicSharedMemorySize,
                         ATTN_SMEM_BYTES);

    // 1) qkv = X @ Wqkv     [32768,1152] = [32768,384]@[384,1152]
    dim3 g1(3 * CC / 128, BB * TT / 128);       // (9, 256)
    gemm_tf32x1<<<g1, 512, GEMM_SMEM_BYTES>>>(X, Wqkv, qkv, BB * TT, 3 * CC, CC);

    // 2) fused causal attention -> att [32768,384]
    attn_kernel<<<BB * HH, 256, ATTN_SMEM_BYTES>>>(qkv, att);

    // 3) out = att @ Wproj  [32768,384] = [32768,384]@[384,384]
    dim3 g3(CC / 128, BB * TT / 128);           // (3, 256)
    gemm_tf32x1<<<g3, 512, GEMM_SMEM_BYTES>>>(att, Wproj, out, BB * TT, CC, CC);
}

// round 9
// speedup vs baseline: 2.0445x; 1.1122x over previous
#include <cuda_runtime.h>
#include <cstdint>
#include <cstddef>

#define BB  128
#define TT  256
#define CC  384
#define HH  6
#define DD  64
#define LDQKV (3*CC)   // 1152

typedef unsigned long long u64;

// Scratch (device globals: allocation-free per harness rules)
__device__ float g_qkv[(size_t)BB * TT * 3 * CC];   // [32768][1152]
__device__ float g_att[(size_t)BB * TT * CC];       // [32768][384]
__device__ float g_rX[(size_t)BB * TT * CC];        // tf32-rounded X
__device__ float g_rW[(size_t)3*CC*CC + (size_t)CC*CC];  // rounded Wqkv | Wproj

// ---------- tf32 helpers ----------
__device__ __forceinline__ float tf32_big(float f) {
    uint32_t r; asm("cvt.rna.tf32.f32 %0, %1;" : "=r"(r) : "f"(f));
    return __uint_as_float(r);
}
__device__ __forceinline__ void mma8(float* c, const uint32_t* a, const uint32_t* b) {
    asm volatile("mma.sync.aligned.m16n8k8.row.col.f32.tf32.tf32.f32 "
        "{%0,%1,%2,%3}, {%4,%5,%6,%7}, {%8,%9}, {%0,%1,%2,%3};"
        : "+f"(c[0]), "+f"(c[1]), "+f"(c[2]), "+f"(c[3])
        : "r"(a[0]), "r"(a[1]), "r"(a[2]), "r"(a[3]), "r"(b[0]), "r"(b[1]));
}
__device__ __forceinline__ uint32_t smem_u32(const void* p) {
    uint32_t a;
    asm("{ .reg .u64 t; cvta.to.shared.u64 t, %1; cvt.u32.u64 %0, t; }"
        : "=r"(a) : "l"(p));
    return a;
}
#define CP_ASYNC16(dst, src) \
    asm volatile("cp.async.cg.shared.global [%0], [%1], 16;" :: "r"(dst), "l"(src))
#define CP_COMMIT()  asm volatile("cp.async.commit_group;" ::: "memory")
#define CP_WAIT1()   asm volatile("cp.async.wait_group 1;" ::: "memory")
#define CP_WAIT0()   asm volatile("cp.async.wait_group 0;" ::: "memory")

// ============================================================
// Pre-round pass: out[i] = tf32_rna(in[i]).  n % 4 == 0.
// ============================================================
__global__ __launch_bounds__(256)
void round_tf32(const float* __restrict__ in, float* __restrict__ out, int n)
{
    int i = (blockIdx.x * 256 + threadIdx.x) * 4;
    if (i < n) {
        float4 v = *(const float4*)(in + i);
        v.x = tf32_big(v.x); v.y = tf32_big(v.y);
        v.z = tf32_big(v.z); v.w = tf32_big(v.w);
        *(float4*)(out + i) = v;
    }
}

// ============================================================
// GEMM 1xTF32, 64x64 warp tiles, cp.async double-buffered.
// C[M,N] = A[M,K] @ B[K,N]; A,B pre-rounded tf32-in-fp32.
// CTA 128x128, 128 threads (4 warps, 2x2), BK=32.
// smem/stage: A [128][36] + B [32][136]  (conflict-free verified).
// ============================================================
#define ASTRIDE 36
#define BSTRIDE 136
#define STG_FLOATS (128*ASTRIDE + 32*BSTRIDE)     // 8960
#define GEMM_SMEM_BYTES (2 * STG_FLOATS * 4)      // 71680

__global__ __launch_bounds__(128)
void gemm_tc64(const float* __restrict__ A, const float* __restrict__ B,
               float* __restrict__ Cm, int M, int N, int K)
{
    extern __shared__ __align__(16) float sm[];
    const uint32_t sbase = smem_u32(sm);

    const int tid  = threadIdx.x;
    const int lane = tid & 31;
    const int warp = tid >> 5;
    const int bm = blockIdx.y * 128;
    const int bn = blockIdx.x * 128;
    const int wm = (warp >> 1) * 64;
    const int wn = (warp & 1) * 64;
    const int g = lane >> 2;   // 0..7
    const int t = lane & 3;    // 0..3

    // cp.async source mapping
    const float* Asrc = A + (size_t)(bm + tid) * K;                    // row tid, 8x16B
    const int brow = tid >> 2;                                          // 0..31
    const int bc0  = (tid & 3) * 32;                                    // float base
    const float* Bsrc = B + (size_t)brow * N + bn + bc0;                // 8x16B
    const uint32_t dA = sbase + (uint32_t)tid * ASTRIDE * 4;
    const uint32_t dB = sbase + (128 * ASTRIDE + brow * BSTRIDE + bc0) * 4;

    float acc[4][8][4];
    #pragma unroll
    for (int i = 0; i < 4; i++)
        #pragma unroll
        for (int j = 0; j < 8; j++)
            #pragma unroll
            for (int l = 0; l < 4; l++) acc[i][j][l] = 0.f;

    const int KT = K >> 5;

    // prologue: stage k-chunk 0 into buffer 0
    {
        const float* a = Asrc;
        #pragma unroll
        for (int c = 0; c < 8; c++) CP_ASYNC16(dA + c * 16, a + c * 4);
        const float* b = Bsrc;
        #pragma unroll
        for (int c = 0; c < 8; c++) CP_ASYNC16(dB + c * 16, b + c * 4);
        CP_COMMIT();
    }

    for (int i = 0; i < KT; i++) {
        const int st = i & 1;
        if (i + 1 < KT) {   // stage next chunk into other buffer
            const uint32_t off = (uint32_t)((st ^ 1) * STG_FLOATS * 4);
            const float* a = Asrc + (i + 1) * 32;
            #pragma unroll
            for (int c = 0; c < 8; c++) CP_ASYNC16(dA + off + c * 16, a + c * 4);
            const float* b = Bsrc + (size_t)(i + 1) * 32 * N;
            #pragma unroll
            for (int c = 0; c < 8; c++) CP_ASYNC16(dB + off + c * 16, b + c * 4);
            CP_COMMIT();
            CP_WAIT1();
        } else {
            CP_WAIT0();
        }
        __syncthreads();

        const float* As = sm + st * STG_FLOATS;
        const float* Bs = As + 128 * ASTRIDE;

        #pragma unroll
        for (int s = 0; s < 4; s++) {
            const int kc = s * 8 + t;
            uint32_t af[4][4], bf[8][2];
            #pragma unroll
            for (int mt = 0; mt < 4; mt++) {
                const int r0 = (wm + mt * 16 + g) * ASTRIDE + kc;
                af[mt][0] = __float_as_uint(As[r0]);
                af[mt][1] = __float_as_uint(As[r0 + 8 * ASTRIDE]);
                af[mt][2] = __float_as_uint(As[r0 + 4]);
                af[mt][3] = __float_as_uint(As[r0 + 8 * ASTRIDE + 4]);
            }
            #pragma unroll
            for (int nt = 0; nt < 8; nt++) {
                const int c0 = kc * BSTRIDE + wn + nt * 8 + g;
                bf[nt][0] = __float_as_uint(Bs[c0]);
                bf[nt][1] = __float_as_uint(Bs[c0 + 4 * BSTRIDE]);
            }
            #pragma unroll
            for (int mt = 0; mt < 4; mt++)
                #pragma unroll
                for (int nt = 0; nt < 8; nt++)
                    mma8(acc[mt][nt], af[mt], bf[nt]);
        }
        __syncthreads();   // all threads done reading buf st (it is re-staged next iter)
    }

    // epilogue
    #pragma unroll
    for (int mt = 0; mt < 4; mt++)
        #pragma unroll
        for (int nt = 0; nt < 8; nt++) {
            const int row = bm + wm + mt * 16 + g;
            const int col = bn + wn + nt * 8 + 2 * t;
            *(float2*)&Cm[(size_t)row * N + col] =
                make_float2(acc[mt][nt][0], acc[mt][nt][1]);
            *(float2*)&Cm[(size_t)(row + 8) * N + col] =
                make_float2(acc[mt][nt][2], acc[mt][nt][3]);
        }
}

// ============================================================
// Tensor-core fused causal attention per (b, h).
// (R4-verified; epilogue now writes tf32-rounded att so the
// proj GEMM can consume it directly via cp.async.)
// ============================================================
#define KTS 264
#define VSS 72
#define PSS 260
#define QSS 68
#define ATTN_SMEM_FLOATS (64*KTS + 256*VSS + 64*PSS + 64*QSS + 64)  // 56384
#define ATTN_SMEM_BYTES  (ATTN_SMEM_FLOATS * 4)                      // 225536

__global__ __launch_bounds__(256, 1)
void attn_kernel(const float* __restrict__ qkv, float* __restrict__ att)
{
    extern __shared__ __align__(16) float smf[];
    float* Kt   = smf;                  // [64][264]   Kt[d][tok]
    float* Vs   = Kt + 64 * KTS;        // [256][72]   Vs[tok][d]
    float* Ps   = Vs + 256 * VSS;       // [64][260]   scores/probs row-major
    float* Qs   = Ps + 64 * PSS;        // [64][68]    Qs[qi][d]
    float* rsum = Qs + 64 * QSS;        // [64]

    const int tid  = threadIdx.x;
    const int lane = tid & 31;
    const int warp = tid >> 5;
    const int warpM = warp >> 2;        // 0..1
    const int warpN = warp & 3;         // 0..3
    const int g = lane >> 2;            // 0..7
    const int t = lane & 3;             // 0..3

    const int b = blockIdx.x / HH;
    const int h = blockIdx.x % HH;
    const float* base = qkv + (size_t)b * TT * LDQKV;
    const float scale = 0.05103103630798288f;  // 384^-0.5 (full-embed quirk)

    // ---- Stage K (transposed, tf32) and V (tf32) ----
    {
        const int d4 = (tid & 15) * 4;
        for (int tok = tid >> 4; tok < TT; tok += 16) {
            const float* row = base + (size_t)tok * LDQKV + h * DD + d4;
            float4 kv = *(const float4*)(row);                 // K at offset 0
            Kt[(d4+0)*KTS + tok] = tf32_big(kv.x);
            Kt[(d4+1)*KTS + tok] = tf32_big(kv.y);
            Kt[(d4+2)*KTS + tok] = tf32_big(kv.z);
            Kt[(d4+3)*KTS + tok] = tf32_big(kv.w);
            float4 vv = *(const float4*)(row + 2*CC);          // V at offset 2C
            vv.x = tf32_big(vv.x); vv.y = tf32_big(vv.y);
            vv.z = tf32_big(vv.z); vv.w = tf32_big(vv.w);
            *(float4*)&Vs[tok*VSS + d4] = vv;
        }
    }

    for (int qt = 0; qt < 4; qt++) {
        __syncthreads();
        // ---- Stage Q tile (row-major, tf32) ----
        {
            const int d4 = (tid & 15) * 4;
            #pragma unroll
            for (int qi = tid >> 4; qi < 64; qi += 16) {
                float4 qv = *(const float4*)(base + (size_t)(qt*64 + qi) * LDQKV
                                             + CC + h * DD + d4);   // Q at offset C
                qv.x = tf32_big(qv.x); qv.y = tf32_big(qv.y);
                qv.z = tf32_big(qv.z); qv.w = tf32_big(qv.w);
                *(float4*)&Qs[qi*QSS + d4] = qv;
            }
        }
        __syncthreads();

        // ---- QK^T: S[64, 256] = Q @ K^T, skip warp-cols above diagonal ----
        if (warpN <= qt) {
            const int wm = warpM * 32;
            const int wn0 = warpN * 64;
            float acc[2][8][4];
            #pragma unroll
            for (int i = 0; i < 2; i++)
                #pragma unroll
                for (int j = 0; j < 8; j++)
                    #pragma unroll
                    for (int l = 0; l < 4; l++) acc[i][j][l] = 0.f;

            #pragma unroll
            for (int s = 0; s < 8; s++) {
                const int kc = s * 8 + t;
                uint32_t af[2][4], bf[8][2];
                #pragma unroll
                for (int mt = 0; mt < 2; mt++) {
                    const int r0 = (wm + mt * 16 + g) * QSS + kc;
                    af[mt][0] = __float_as_uint(Qs[r0]);
                    af[mt][1] = __float_as_uint(Qs[r0 + 8 * QSS]);
                    af[mt][2] = __float_as_uint(Qs[r0 + 4]);
                    af[mt][3] = __float_as_uint(Qs[r0 + 8 * QSS + 4]);
                }
                #pragma unroll
                for (int nt = 0; nt < 8; nt++) {
                    const int c0 = kc * KTS + wn0 + nt * 8 + g;
                    bf[nt][0] = __float_as_uint(Kt[c0]);
                    bf[nt][1] = __float_as_uint(Kt[c0 + 4 * KTS]);
                }
                #pragma unroll
                for (int mt = 0; mt < 2; mt++)
                    #pragma unroll
                    for (int nt = 0; nt < 8; nt++)
                        mma8(acc[mt][nt], af[mt], bf[nt]);
            }
            #pragma unroll
            for (int mt = 0; mt < 2; mt++)
                #pragma unroll
                for (int nt = 0; nt < 8; nt++) {
                    const int row = wm + mt * 16 + g;
                    const int col = wn0 + nt * 8 + 2 * t;
                    *(float2*)&Ps[row * PSS + col] =
                        make_float2(acc[mt][nt][0], acc[mt][nt][1]);
                    *(float2*)&Ps[(row + 8) * PSS + col] =
                        make_float2(acc[mt][nt][2], acc[mt][nt][3]);
                }
        }
        __syncthreads();

        // ---- causal softmax over rows of Ps; store tf32-rounded P ----
        {
            const int nj = (qt + 1) * 64;
            #pragma unroll
            for (int rr = 0; rr < 8; rr++) {
                const int qi = warp * 8 + rr;
                const int nv = qt * 64 + qi + 1;   // valid j in [0, nv)
                float m = -1e30f;
                for (int j = lane; j < nv; j += 32) m = fmaxf(m, Ps[qi*PSS + j]);
                #pragma unroll
                for (int o = 16; o; o >>= 1) m = fmaxf(m, __shfl_xor_sync(0xffffffffu, m, o));
                m *= scale;
                float ssum = 0.f;
                for (int j = lane; j < nj; j += 32) {
                    float p = (j < nv) ? __expf(Ps[qi*PSS + j] * scale - m) : 0.f;
                    Ps[qi*PSS + j] = tf32_big(p);
                    ssum += p;
                }
                #pragma unroll
                for (int o = 16; o; o >>= 1) ssum += __shfl_xor_sync(0xffffffffu, ssum, o);
                if (lane == 0) rsum[qi] = 1.f / ssum;
            }
        }
        __syncthreads();

        // ---- PV: O[64, 64] = P[64, nj] @ V[nj, 64] ----
        {
            const int wm = warpM * 32;
            const int wn = warpN * 16;
            const int KS = (qt + 1) * 8;    // k-steps (causal truncation)
            float acc[2][2][4];
            #pragma unroll
            for (int i = 0; i < 2; i++)
                #pragma unroll
                for (int j = 0; j < 2; j++)
                    #pragma unroll
                    for (int l = 0; l < 4; l++) acc[i][j][l] = 0.f;

            for (int s = 0; s < KS; s++) {
                const int kc = s * 8 + t;
                uint32_t af[2][4], bf[2][2];
                #pragma unroll
                for (int mt = 0; mt < 2; mt++) {
                    const int r0 = (wm + mt * 16 + g) * PSS + kc;
                    af[mt][0] = __float_as_uint(Ps[r0]);
                    af[mt][1] = __float_as_uint(Ps[r0 + 8 * PSS]);
                    af[mt][2] = __float_as_uint(Ps[r0 + 4]);
                    af[mt][3] = __float_as_uint(Ps[r0 + 8 * PSS + 4]);
                }
                #pragma unroll
                for (int nt = 0; nt < 2; nt++) {
                    const int c0 = kc * VSS + wn + nt * 8 + g;
                    bf[nt][0] = __float_as_uint(Vs[c0]);
                    bf[nt][1] = __float_as_uint(Vs[c0 + 4 * VSS]);
                }
                #pragma unroll
                for (int mt = 0; mt < 2; mt++)
                    #pragma unroll
                    for (int nt = 0; nt < 2; nt++)
                        mma8(acc[mt][nt], af[mt], bf[nt]);
            }
            #pragma unroll
            for (int mt = 0; mt < 2; mt++)
                #pragma unroll
                for (int nt = 0; nt < 2; nt++) {
                    const int row = wm + mt * 16 + g;
                    const int col = wn + nt * 8 + 2 * t;
                    const float s0 = rsum[row], s1 = rsum[row + 8];
                    size_t r0 = ((size_t)b * TT + qt*64 + row) * CC + h * DD + col;
                    *(float2*)&att[r0] = make_float2(
                        tf32_big(acc[mt][nt][0] * s0), tf32_big(acc[mt][nt][1] * s0));
                    *(float2*)&att[r0 + (size_t)8 * CC] = make_float2(
                        tf32_big(acc[mt][nt][2] * s1), tf32_big(acc[mt][nt][3] * s1));
                }
        }
    }
}

// ============================================================
extern "C" void kernel_launch(void* const* d_in, const int* in_sizes, int n_in,
                              void* d_out, int out_size)
{
    const float* X     = (const float*)d_in[0];
    const float* Wqkv  = (const float*)d_in[1];
    const float* Wproj = (const float*)d_in[2];
    float* out = (float*)d_out;

    void *p0, *p1, *p2, *p3;
    cudaGetSymbolAddress(&p0, g_qkv);
    cudaGetSymbolAddress(&p1, g_att);
    cudaGetSymbolAddress(&p2, g_rX);
    cudaGetSymbolAddress(&p3, g_rW);
    float* qkv   = (float*)p0;
    float* att   = (float*)p1;
    float* rX    = (float*)p2;
    float* rWqkv = (float*)p3;
    float* rWproj = rWqkv + (size_t)3 * CC * CC;

    cudaFuncSetAttribute(gemm_tc64, cudaFuncAttributeMaxDynamicSharedMemorySize,
                         GEMM_SMEM_BYTES);
    cudaFuncSetAttribute(attn_kernel, cudaFuncAttributeMaxDynamicSharedMemorySize,
                         ATTN_SMEM_BYTES);

    // 0) pre-round X and weights to tf32 (rna)
    const int nX = BB * TT * CC;
    round_tf32<<<(nX / 4 + 255) / 256, 256>>>(X, rX, nX);
    const int nW1 = 3 * CC * CC;
    round_tf32<<<(nW1 / 4 + 255) / 256, 256>>>(Wqkv, rWqkv, nW1);
    const int nW2 = CC * CC;
    round_tf32<<<(nW2 / 4 + 255) / 256, 256>>>(Wproj, rWproj, nW2);

    // 1) qkv = rX @ rWqkv   [32768,1152]
    dim3 g1(3 * CC / 128, BB * TT / 128);       // (9, 256)
    gemm_tc64<<<g1, 128, GEMM_SMEM_BYTES>>>(rX, rWqkv, qkv, BB * TT, 3 * CC, CC);

    // 2) fused causal attention -> att (tf32-rounded)
    attn_kernel<<<BB * HH, 256, ATTN_SMEM_BYTES>>>(qkv, att);

    // 3) out = att @ rWproj [32768,384]
    dim3 g3(CC / 128, BB * TT / 128);           // (3, 256)
    gemm_tc64<<<g3, 128, GEMM_SMEM_BYTES>>>(att, rWproj, out, BB * TT, CC, CC);
}

// round 13
// speedup vs baseline: 2.9699x; 1.4526x over previous
#include <cuda_runtime.h>
#include <cstdint>
#include <cstddef>

#define BB  128
#define TT  256
#define CC  384
#define HH  6
#define DD  64
#define LDQKV (3*CC)   // 1152

typedef unsigned long long u64;

// Scratch (device globals: allocation-free per harness rules)
__device__ float g_qkv[(size_t)BB * TT * 3 * CC];   // [32768][1152] row-major
__device__ float g_att[(size_t)BB * TT * CC];       // att in A-perm layout
__device__ float g_pX[(size_t)BB * TT * CC];        // X in A-perm layout (tf32)
__device__ float g_pW[(size_t)3*CC*CC + (size_t)CC*CC];  // Wqkv|Wproj B-perm (tf32)

// ---------- tf32 helpers ----------
__device__ __forceinline__ float tf32_big(float f) {
    uint32_t r; asm("cvt.rna.tf32.f32 %0, %1;" : "=r"(r) : "f"(f));
    return __uint_as_float(r);
}
__device__ __forceinline__ void mma8(float* c, const uint32_t* a, const uint32_t* b) {
    asm volatile("mma.sync.aligned.m16n8k8.row.col.f32.tf32.tf32.f32 "
        "{%0,%1,%2,%3}, {%4,%5,%6,%7}, {%8,%9}, {%0,%1,%2,%3};"
        : "+f"(c[0]), "+f"(c[1]), "+f"(c[2]), "+f"(c[3])
        : "r"(a[0]), "r"(a[1]), "r"(a[2]), "r"(a[3]), "r"(b[0]), "r"(b[1]));
}
__device__ __forceinline__ uint32_t smem_u32(const void* p) {
    uint32_t a;
    asm("{ .reg .u64 t; cvta.to.shared.u64 t, %1; cvt.u32.u64 %0, t; }"
        : "=r"(a) : "l"(p));
    return a;
}
#define CP_ASYNC16(dst, src) \
    asm volatile("cp.async.cg.shared.global [%0], [%1], 16;" :: "r"(dst), "l"(src))
#define CP_COMMIT()  asm volatile("cp.async.commit_group;" ::: "memory")
#define CP_WAIT1()   asm volatile("cp.async.wait_group 1;" ::: "memory")
#define CP_WAIT0()   asm volatile("cp.async.wait_group 0;" ::: "memory")

// ============================================================
// A-perm layout (tf32-rounded), for A[M][K], K%32==0, M%128==0:
//   addr = ((row>>7)*(K/32) + (col>>5))*4096
//        + ((col>>3)&3)*1024 + ((row&127)>>4)*128
//        + ((row&7)*4 + (col&3))*4 + ((col&7)>=4 ? 2 : 0) + ((row>>3)&1)
// packet (4 floats) = a0,a1,a2,a3 of one mma fragment.
// ============================================================
__global__ __launch_bounds__(256)
void perm_a(const float* __restrict__ in, float* __restrict__ out, int M, int K)
{
    const int pk = blockIdx.x * 256 + threadIdx.x;         // packet id
    const int perTile = (K >> 5) * 1024;                   // packets per 128-row tile
    if (pk >= (M >> 7) * perTile) return;
    const int mtile = pk / perTile;
    int rem = pk - mtile * perTile;
    const int kc = rem >> 10;
    const int pp = rem & 1023;
    const int s = pp >> 8, mgrp = (pp >> 5) & 7, lane = pp & 31;
    const int g = lane >> 2, t = lane & 3;
    const int row = mtile * 128 + mgrp * 16 + g;
    const int col = kc * 32 + s * 8 + t;
    float4 v;
    v.x = tf32_big(in[(size_t)row * K + col]);
    v.y = tf32_big(in[(size_t)(row + 8) * K + col]);
    v.z = tf32_big(in[(size_t)row * K + col + 4]);
    v.w = tf32_big(in[(size_t)(row + 8) * K + col + 4]);
    *(float4*)(out + (size_t)pk * 4) = v;
}

// ============================================================
// B-perm layout (tf32-rounded), for B[K][N]:
//   packet (2 floats) per (kchunk, s, cgrp, lane): B[kc][col], B[kc+4][col]
//   with kc = kchunk*32+s*8+t, col = cgrp*8+g, lane = 4g+t.
// ============================================================
__global__ __launch_bounds__(256)
void perm_b(const float* __restrict__ in, float* __restrict__ out, int K, int N)
{
    const int pk = blockIdx.x * 256 + threadIdx.x;
    if (pk >= (K * N) >> 1) return;
    const int perS = (N >> 3) * 32;          // packets per (kchunk,s)
    const int kch = pk / (perS * 4);
    int rem = pk - kch * perS * 4;
    const int s = rem / perS;
    rem -= s * perS;
    const int cg = rem >> 5, lane = rem & 31;
    const int g = lane >> 2, t = lane & 3;
    const int krow = kch * 32 + s * 8 + t;
    const int col = cg * 8 + g;
    float2 v;
    v.x = tf32_big(in[(size_t)krow * N + col]);
    v.y = tf32_big(in[(size_t)(krow + 4) * N + col]);
    *(float2*)(out + (size_t)pk * 2) = v;
}

// ============================================================
// GEMM on permuted operands: C[M,N] = A @ B (row-major C).
// CTA 128x128, 128 threads (4 warps, 2x2 of 64x64), BK=32.
// 3-stage cp.async ring; A frags via LDS.128, B via LDS.64.
// ============================================================
#define STG 8192                              // floats/stage: A 4096 | B 4096
#define GEMM_SMEM_BYTES (3 * STG * 4)         // 98304

__global__ __launch_bounds__(128)
void gemm_p(const float* __restrict__ Ap, const float* __restrict__ Bp,
            float* __restrict__ Cm, int M, int N, int K)
{
    extern __shared__ __align__(16) float sm[];
    const uint32_t sbase = smem_u32(sm);

    const int tid  = threadIdx.x;
    const int lane = tid & 31;
    const int warp = tid >> 5;
    const int bm = blockIdx.y * 128;
    const int bn = blockIdx.x * 128;
    const int wmg = (warp >> 1) * 4;          // m-group base (16-row groups)
    const int wng = (warp & 1) * 8;           // n-group base (8-col groups)
    const int g = lane >> 2;
    const int t = lane & 3;

    const int KT = K >> 5;
    const float* Abase = Ap + (size_t)blockIdx.y * K * 128;   // mtile*KT*4096
    const size_t bn8 = (size_t)(bn >> 3);
    const int n8 = N >> 3;

    float acc[4][8][4];
    #pragma unroll
    for (int i = 0; i < 4; i++)
        #pragma unroll
        for (int j = 0; j < 8; j++)
            #pragma unroll
            for (int l = 0; l < 4; l++) acc[i][j][l] = 0.f;

    // stage chunk i into ring buffer buf
    #define STAGE(i, buf) do {                                                  \
        const uint32_t d = sbase + (uint32_t)(buf) * STG * 4;                   \
        const float* asrc = Abase + (size_t)(i) * 4096;                         \
        _Pragma("unroll")                                                       \
        for (int j = 0; j < 8; j++) {                                           \
            const int p = tid + 128 * j;                                        \
            CP_ASYNC16(d + p * 16, asrc + p * 4);                               \
        }                                                                       \
        _Pragma("unroll")                                                       \
        for (int j = 0; j < 8; j++) {                                           \
            const int p = tid + 128 * j;                                        \
            const int ss = p >> 8, w = p & 255;                                 \
            const float* bsrc = Bp + ((size_t)((i) * 4 + ss) * n8 + bn8) * 64   \
                                + w * 4;                                        \
            CP_ASYNC16(d + 16384 + p * 16, bsrc);                               \
        }                                                                       \
    } while (0)

    STAGE(0, 0); CP_COMMIT();
    STAGE(1, 1); CP_COMMIT();

    int buf = 0;
    for (int i = 0; i < KT; i++) {
        if (i + 1 < KT) CP_WAIT1(); else CP_WAIT0();
        __syncthreads();
        if (i + 2 < KT) { STAGE(i + 2, (buf + 2) % 3); CP_COMMIT(); }

        const float* As = sm + buf * STG;
        const float* Bs = As + 4096;
        #pragma unroll
        for (int s = 0; s < 4; s++) {
            uint32_t af[4][4], bf[8][2];
            #pragma unroll
            for (int mt = 0; mt < 4; mt++) {
                float4 va = *(const float4*)&As[s * 1024 + (wmg + mt) * 128 + lane * 4];
                af[mt][0] = __float_as_uint(va.x); af[mt][1] = __float_as_uint(va.y);
                af[mt][2] = __float_as_uint(va.z); af[mt][3] = __float_as_uint(va.w);
            }
            #pragma unroll
            for (int nt = 0; nt < 8; nt++) {
                float2 vb = *(const float2*)&Bs[s * 1024 + (wng + nt) * 64 + lane * 2];
                bf[nt][0] = __float_as_uint(vb.x); bf[nt][1] = __float_as_uint(vb.y);
            }
            #pragma unroll
            for (int mt = 0; mt < 4; mt++)
                #pragma unroll
                for (int nt = 0; nt < 8; nt++)
                    mma8(acc[mt][nt], af[mt], bf[nt]);
        }
        buf++; if (buf == 3) buf = 0;
    }
    #undef STAGE

    // epilogue: row-major C
    const int wm = (warp >> 1) * 64;
    const int wn = (warp & 1) * 64;
    #pragma unroll
    for (int mt = 0; mt < 4; mt++)
        #pragma unroll
        for (int nt = 0; nt < 8; nt++) {
            const int row = bm + wm + mt * 16 + g;
            const int col = bn + wn + nt * 8 + 2 * t;
            *(float2*)&Cm[(size_t)row * N + col] =
                make_float2(acc[mt][nt][0], acc[mt][nt][1]);
            *(float2*)&Cm[(size_t)(row + 8) * N + col] =
                make_float2(acc[mt][nt][2], acc[mt][nt][3]);
        }
}

// ============================================================
// Tensor-core fused causal attention per (b, h).  (R4-verified)
// Epilogue writes att in A-perm layout (tf32-rounded).
// ============================================================
#define KTS 264
#define VSS 72
#define PSS 260
#define QSS 68
#define ATTN_SMEM_FLOATS (64*KTS + 256*VSS + 64*PSS + 64*QSS + 64)  // 56384
#define ATTN_SMEM_BYTES  (ATTN_SMEM_FLOATS * 4)                      // 225536

__global__ __launch_bounds__(256, 1)
void attn_kernel(const float* __restrict__ qkv, float* __restrict__ att)
{
    extern __shared__ __align__(16) float smf[];
    float* Kt   = smf;                  // [64][264]   Kt[d][tok]
    float* Vs   = Kt + 64 * KTS;        // [256][72]   Vs[tok][d]
    float* Ps   = Vs + 256 * VSS;       // [64][260]   scores/probs row-major
    float* Qs   = Ps + 64 * PSS;        // [64][68]    Qs[qi][d]
    float* rsum = Qs + 64 * QSS;        // [64]

    const int tid  = threadIdx.x;
    const int lane = tid & 31;
    const int warp = tid >> 5;
    const int warpM = warp >> 2;        // 0..1
    const int warpN = warp & 3;         // 0..3
    const int g = lane >> 2;            // 0..7
    const int t = lane & 3;             // 0..3

    const int b = blockIdx.x / HH;
    const int h = blockIdx.x % HH;
    const float* base = qkv + (size_t)b * TT * LDQKV;
    const float scale = 0.05103103630798288f;  // 384^-0.5 (full-embed quirk)

    // ---- Stage K (transposed, tf32) and V (tf32) ----
    {
        const int d4 = (tid & 15) * 4;
        for (int tok = tid >> 4; tok < TT; tok += 16) {
            const float* row = base + (size_t)tok * LDQKV + h * DD + d4;
            float4 kv = *(const float4*)(row);                 // K at offset 0
            Kt[(d4+0)*KTS + tok] = tf32_big(kv.x);
            Kt[(d4+1)*KTS + tok] = tf32_big(kv.y);
            Kt[(d4+2)*KTS + tok] = tf32_big(kv.z);
            Kt[(d4+3)*KTS + tok] = tf32_big(kv.w);
            float4 vv = *(const float4*)(row + 2*CC);          // V at offset 2C
            vv.x = tf32_big(vv.x); vv.y = tf32_big(vv.y);
            vv.z = tf32_big(vv.z); vv.w = tf32_big(vv.w);
            *(float4*)&Vs[tok*VSS + d4] = vv;
        }
    }

    for (int qt = 0; qt < 4; qt++) {
        __syncthreads();
        // ---- Stage Q tile (row-major, tf32) ----
        {
            const int d4 = (tid & 15) * 4;
            #pragma unroll
            for (int qi = tid >> 4; qi < 64; qi += 16) {
                float4 qv = *(const float4*)(base + (size_t)(qt*64 + qi) * LDQKV
                                             + CC + h * DD + d4);   // Q at offset C
                qv.x = tf32_big(qv.x); qv.y = tf32_big(qv.y);
                qv.z = tf32_big(qv.z); qv.w = tf32_big(qv.w);
                *(float4*)&Qs[qi*QSS + d4] = qv;
            }
        }
        __syncthreads();

        // ---- QK^T: S[64, 256] = Q @ K^T, skip warp-cols above diagonal ----
        if (warpN <= qt) {
            const int wm = warpM * 32;
            const int wn0 = warpN * 64;
            float acc[2][8][4];
            #pragma unroll
            for (int i = 0; i < 2; i++)
                #pragma unroll
                for (int j = 0; j < 8; j++)
                    #pragma unroll
                    for (int l = 0; l < 4; l++) acc[i][j][l] = 0.f;

            #pragma unroll
            for (int s = 0; s < 8; s++) {
                const int kc = s * 8 + t;
                uint32_t af[2][4], bf[8][2];
                #pragma unroll
                for (int mt = 0; mt < 2; mt++) {
                    const int r0 = (wm + mt * 16 + g) * QSS + kc;
                    af[mt][0] = __float_as_uint(Qs[r0]);
                    af[mt][1] = __float_as_uint(Qs[r0 + 8 * QSS]);
                    af[mt][2] = __float_as_uint(Qs[r0 + 4]);
                    af[mt][3] = __float_as_uint(Qs[r0 + 8 * QSS + 4]);
                }
                #pragma unroll
                for (int nt = 0; nt < 8; nt++) {
                    const int c0 = kc * KTS + wn0 + nt * 8 + g;
                    bf[nt][0] = __float_as_uint(Kt[c0]);
                    bf[nt][1] = __float_as_uint(Kt[c0 + 4 * KTS]);
                }
                #pragma unroll
                for (int mt = 0; mt < 2; mt++)
                    #pragma unroll
                    for (int nt = 0; nt < 8; nt++)
                        mma8(acc[mt][nt], af[mt], bf[nt]);
            }
            #pragma unroll
            for (int mt = 0; mt < 2; mt++)
                #pragma unroll
                for (int nt = 0; nt < 8; nt++) {
                    const int row = wm + mt * 16 + g;
                    const int col = wn0 + nt * 8 + 2 * t;
                    *(float2*)&Ps[row * PSS + col] =
                        make_float2(acc[mt][nt][0], acc[mt][nt][1]);
                    *(float2*)&Ps[(row + 8) * PSS + col] =
                        make_float2(acc[mt][nt][2], acc[mt][nt][3]);
                }
        }
        __syncthreads();

        // ---- causal softmax over rows of Ps; store tf32-rounded P ----
        {
            const int nj = (qt + 1) * 64;
            #pragma unroll
            for (int rr = 0; rr < 8; rr++) {
                const int qi = warp * 8 + rr;
                const int nv = qt * 64 + qi + 1;   // valid j in [0, nv)
                float m = -1e30f;
                for (int j = lane; j < nv; j += 32) m = fmaxf(m, Ps[qi*PSS + j]);
                #pragma unroll
                for (int o = 16; o; o >>= 1) m = fmaxf(m, __shfl_xor_sync(0xffffffffu, m, o));
                m *= scale;
                float ssum = 0.f;
                for (int j = lane; j < nj; j += 32) {
                    float p = (j < nv) ? __expf(Ps[qi*PSS + j] * scale - m) : 0.f;
                    Ps[qi*PSS + j] = tf32_big(p);
                    ssum += p;
                }
                #pragma unroll
                for (int o = 16; o; o >>= 1) ssum += __shfl_xor_sync(0xffffffffu, ssum, o);
                if (lane == 0) rsum[qi] = 1.f / ssum;
            }
        }
        __syncthreads();

        // ---- PV: O[64, 64] = P[64, nj] @ V[nj, 64] ----
        {
            const int wm = warpM * 32;
            const int wn = warpN * 16;
            const int KS = (qt + 1) * 8;    // k-steps (causal truncation)
            float acc[2][2][4];
            #pragma unroll
            for (int i = 0; i < 2; i++)
                #pragma unroll
                for (int j = 0; j < 2; j++)
                    #pragma unroll
                    for (int l = 0; l < 4; l++) acc[i][j][l] = 0.f;

            for (int s = 0; s < KS; s++) {
                const int kc = s * 8 + t;
                uint32_t af[2][4], bf[2][2];
                #pragma unroll
                for (int mt = 0; mt < 2; mt++) {
                    const int r0 = (wm + mt * 16 + g) * PSS + kc;
                    af[mt][0] = __float_as_uint(Ps[r0]);
                    af[mt][1] = __float_as_uint(Ps[r0 + 8 * PSS]);
                    af[mt][2] = __float_as_uint(Ps[r0 + 4]);
                    af[mt][3] = __float_as_uint(Ps[r0 + 8 * PSS + 4]);
                }
                #pragma unroll
                for (int nt = 0; nt < 2; nt++) {
                    const int c0 = kc * VSS + wn + nt * 8 + g;
                    bf[nt][0] = __float_as_uint(Vs[c0]);
                    bf[nt][1] = __float_as_uint(Vs[c0 + 4 * VSS]);
                }
                #pragma unroll
                for (int mt = 0; mt < 2; mt++)
                    #pragma unroll
                    for (int nt = 0; nt < 2; nt++)
                        mma8(acc[mt][nt], af[mt], bf[nt]);
            }
            // ---- epilogue: write att in A-perm layout (GEMM3 consumes) ----
            #pragma unroll
            for (int mt = 0; mt < 2; mt++)
                #pragma unroll
                for (int nt = 0; nt < 2; nt++) {
                    const int row = wm + mt * 16 + g;             // 0..63
                    const float s0 = rsum[row], s1 = rsum[row + 8];
                    const float v0 = tf32_big(acc[mt][nt][0] * s0);
                    const float v1 = tf32_big(acc[mt][nt][1] * s0);
                    const float v2 = tf32_big(acc[mt][nt][2] * s1);
                    const float v3 = tf32_big(acc[mt][nt][3] * s1);
                    const int rowg = qt * 64 + row;               // 0..255
                    const int mtile = b * 2 + (rowg >> 7);
                    const int r = rowg & 127;
                    const int mgrp = r >> 4;                      // (r&8)==0 here
                    const int col0 = h * DD + wn + nt * 8 + 2 * t;
                    const int kc = col0 >> 5;
                    const int s_ = (col0 >> 3) & 3;
                    const int cw0 = col0 & 7;                     // = 2t
                    const size_t cbase = ((size_t)(mtile * 12 + kc)) * 4096
                                       + s_ * 1024 + mgrp * 128;
                    const int lane0 = g * 4 + (cw0 & 3);
                    const int reg0  = (cw0 >= 4) ? 2 : 0;
                    *(float2*)&att[cbase + lane0 * 4 + reg0] = make_float2(v0, v2);
                    const int cw1 = cw0 + 1;
                    const int lane1 = g * 4 + (cw1 & 3);
                    const int reg1  = (cw1 >= 4) ? 2 : 0;
                    *(float2*)&att[cbase + lane1 * 4 + reg1] = make_float2(v1, v3);
                }
        }
    }
}

// ============================================================
extern "C" void kernel_launch(void* const* d_in, const int* in_sizes, int n_in,
                              void* d_out, int out_size)
{
    const float* X     = (const float*)d_in[0];
    const float* Wqkv  = (const float*)d_in[1];
    const float* Wproj = (const float*)d_in[2];
    float* out = (float*)d_out;

    void *p0, *p1, *p2, *p3;
    cudaGetSymbolAddress(&p0, g_qkv);
    cudaGetSymbolAddress(&p1, g_att);
    cudaGetSymbolAddress(&p2, g_pX);
    cudaGetSymbolAddress(&p3, g_pW);
    float* qkv  = (float*)p0;
    float* att  = (float*)p1;
    float* pX   = (float*)p2;
    float* pWq  = (float*)p3;
    float* pWp  = pWq + (size_t)3 * CC * CC;

    cudaFuncSetAttribute(gemm_p, cudaFuncAttributeMaxDynamicSharedMemorySize,
                         GEMM_SMEM_BYTES);
    cudaFuncSetAttribute(attn_kernel, cudaFuncAttributeMaxDynamicSharedMemorySize,
                         ATTN_SMEM_BYTES);

    // 0) permute+round operands
    const int pkA = (BB * TT / 128) * (CC / 32) * 1024;          // 3.1M packets
    perm_a<<<(pkA + 255) / 256, 256>>>(X, pX, BB * TT, CC);
    const int pkB1 = (CC * 3 * CC) / 2;
    perm_b<<<(pkB1 + 255) / 256, 256>>>(Wqkv, pWq, CC, 3 * CC);
    const int pkB2 = (CC * CC) / 2;
    perm_b<<<(pkB2 + 255) / 256, 256>>>(Wproj, pWp, CC, CC);

    // 1) qkv = X @ Wqkv   [32768,1152]
    dim3 g1(3 * CC / 128, BB * TT / 128);       // (9, 256)
    gemm_p<<<g1, 128, GEMM_SMEM_BYTES>>>(pX, pWq, qkv, BB * TT, 3 * CC, CC);

    // 2) fused causal attention -> att (A-perm layout)
    attn_kernel<<<BB * HH, 256, ATTN_SMEM_BYTES>>>(qkv, att);

    // 3) out = att @ Wproj [32768,384]
    dim3 g3(CC / 128, BB * TT / 128);           // (3, 256)
    gemm_p<<<g3, 128, GEMM_SMEM_BYTES>>>(att, pWp, out, BB * TT, CC, CC);
}

// round 17
// speedup vs baseline: 3.9307x; 1.3235x over previous
#include <cuda_runtime.h>
#include <cstdint>
#include <cstddef>

#define BB  128
#define TT  256
#define CC  384
#define HH  6
#define DD  64
#define LDQKV (3*CC)   // 1152

typedef unsigned long long u64;

// Scratch (device globals: allocation-free per harness rules)
__device__ float g_qkv[(size_t)BB * TT * 3 * CC];   // [32768][1152] row-major
__device__ float g_att[(size_t)BB * TT * CC];       // att in A-perm layout
__device__ float g_pX[(size_t)BB * TT * CC];        // X in A-perm layout (tf32)
__device__ float g_pW[(size_t)3*CC*CC + (size_t)CC*CC];  // Wqkv|Wproj B-perm (tf32)

// ---------- tf32 helpers ----------
__device__ __forceinline__ float tf32_big(float f) {
    uint32_t r; asm("cvt.rna.tf32.f32 %0, %1;" : "=r"(r) : "f"(f));
    return __uint_as_float(r);
}
__device__ __forceinline__ void mma8(float* c, const uint32_t* a, const uint32_t* b) {
    asm volatile("mma.sync.aligned.m16n8k8.row.col.f32.tf32.tf32.f32 "
        "{%0,%1,%2,%3}, {%4,%5,%6,%7}, {%8,%9}, {%0,%1,%2,%3};"
        : "+f"(c[0]), "+f"(c[1]), "+f"(c[2]), "+f"(c[3])
        : "r"(a[0]), "r"(a[1]), "r"(a[2]), "r"(a[3]), "r"(b[0]), "r"(b[1]));
}
__device__ __forceinline__ uint32_t smem_u32(const void* p) {
    uint32_t a;
    asm("{ .reg .u64 t; cvta.to.shared.u64 t, %1; cvt.u32.u64 %0, t; }"
        : "=r"(a) : "l"(p));
    return a;
}
#define CP_ASYNC16(dst, src) \
    asm volatile("cp.async.cg.shared.global [%0], [%1], 16;" :: "r"(dst), "l"(src))
#define CP_COMMIT()  asm volatile("cp.async.commit_group;" ::: "memory")
#define CP_WAIT1()   asm volatile("cp.async.wait_group 1;" ::: "memory")
#define CP_WAIT0()   asm volatile("cp.async.wait_group 0;" ::: "memory")

// ============================================================
// A-perm layout (tf32-rounded), for A[M][K], K%32==0, M%128==0.
// packet (4 floats) = a0,a1,a2,a3 of one mma fragment.
// ============================================================
__global__ __launch_bounds__(256)
void perm_a(const float* __restrict__ in, float* __restrict__ out, int M, int K)
{
    const int pk = blockIdx.x * 256 + threadIdx.x;         // packet id
    const int perTile = (K >> 5) * 1024;                   // packets per 128-row tile
    if (pk >= (M >> 7) * perTile) return;
    const int mtile = pk / perTile;
    int rem = pk - mtile * perTile;
    const int kc = rem >> 10;
    const int pp = rem & 1023;
    const int s = pp >> 8, mgrp = (pp >> 5) & 7, lane = pp & 31;
    const int g = lane >> 2, t = lane & 3;
    const int row = mtile * 128 + mgrp * 16 + g;
    const int col = kc * 32 + s * 8 + t;
    float4 v;
    v.x = tf32_big(in[(size_t)row * K + col]);
    v.y = tf32_big(in[(size_t)(row + 8) * K + col]);
    v.z = tf32_big(in[(size_t)row * K + col + 4]);
    v.w = tf32_big(in[(size_t)(row + 8) * K + col + 4]);
    *(float4*)(out + (size_t)pk * 4) = v;
}

// ============================================================
// B-perm layout (tf32-rounded), for B[K][N].
// ============================================================
__global__ __launch_bounds__(256)
void perm_b(const float* __restrict__ in, float* __restrict__ out, int K, int N)
{
    const int pk = blockIdx.x * 256 + threadIdx.x;
    if (pk >= (K * N) >> 1) return;
    const int perS = (N >> 3) * 32;          // packets per (kchunk,s)
    const int kch = pk / (perS * 4);
    int rem = pk - kch * perS * 4;
    const int s = rem / perS;
    rem -= s * perS;
    const int cg = rem >> 5, lane = rem & 31;
    const int g = lane >> 2, t = lane & 3;
    const int krow = kch * 32 + s * 8 + t;
    const int col = cg * 8 + g;
    float2 v;
    v.x = tf32_big(in[(size_t)krow * N + col]);
    v.y = tf32_big(in[(size_t)(krow + 4) * N + col]);
    *(float2*)(out + (size_t)pk * 2) = v;
}

// ============================================================
// GEMM on permuted operands: C[M,N] = A @ B (row-major C).
// CTA 128x128, 128 threads (4 warps, 2x2 of 64x64), BK=32.
// 3-stage cp.async ring; A frags via LDS.128, B via LDS.64.
// ============================================================
#define STG 8192                              // floats/stage: A 4096 | B 4096
#define GEMM_SMEM_BYTES (3 * STG * 4)         // 98304

__global__ __launch_bounds__(128)
void gemm_p(const float* __restrict__ Ap, const float* __restrict__ Bp,
            float* __restrict__ Cm, int M, int N, int K)
{
    extern __shared__ __align__(16) float sm[];
    const uint32_t sbase = smem_u32(sm);

    const int tid  = threadIdx.x;
    const int lane = tid & 31;
    const int warp = tid >> 5;
    const int bm = blockIdx.y * 128;
    const int bn = blockIdx.x * 128;
    const int wmg = (warp >> 1) * 4;          // m-group base (16-row groups)
    const int wng = (warp & 1) * 8;           // n-group base (8-col groups)
    const int g = lane >> 2;
    const int t = lane & 3;

    const int KT = K >> 5;
    const float* Abase = Ap + (size_t)blockIdx.y * K * 128;   // mtile*KT*4096
    const size_t bn8 = (size_t)(bn >> 3);
    const int n8 = N >> 3;

    float acc[4][8][4];
    #pragma unroll
    for (int i = 0; i < 4; i++)
        #pragma unroll
        for (int j = 0; j < 8; j++)
            #pragma unroll
            for (int l = 0; l < 4; l++) acc[i][j][l] = 0.f;

    #define STAGE(i, buf) do {                                                  \
        const uint32_t d = sbase + (uint32_t)(buf) * STG * 4;                   \
        const float* asrc = Abase + (size_t)(i) * 4096;                         \
        _Pragma("unroll")                                                       \
        for (int j = 0; j < 8; j++) {                                           \
            const int p = tid + 128 * j;                                        \
            CP_ASYNC16(d + p * 16, asrc + p * 4);                               \
        }                                                                       \
        _Pragma("unroll")                                                       \
        for (int j = 0; j < 8; j++) {                                           \
            const int p = tid + 128 * j;                                        \
            const int ss = p >> 8, w = p & 255;                                 \
            const float* bsrc = Bp + ((size_t)((i) * 4 + ss) * n8 + bn8) * 64   \
                                + w * 4;                                        \
            CP_ASYNC16(d + 16384 + p * 16, bsrc);                               \
        }                                                                       \
    } while (0)

    STAGE(0, 0); CP_COMMIT();
    STAGE(1, 1); CP_COMMIT();

    int buf = 0;
    for (int i = 0; i < KT; i++) {
        if (i + 1 < KT) CP_WAIT1(); else CP_WAIT0();
        __syncthreads();
        if (i + 2 < KT) { STAGE(i + 2, (buf + 2) % 3); CP_COMMIT(); }

        const float* As = sm + buf * STG;
        const float* Bs = As + 4096;
        #pragma unroll
        for (int s = 0; s < 4; s++) {
            uint32_t af[4][4], bf[8][2];
            #pragma unroll
            for (int mt = 0; mt < 4; mt++) {
                float4 va = *(const float4*)&As[s * 1024 + (wmg + mt) * 128 + lane * 4];
                af[mt][0] = __float_as_uint(va.x); af[mt][1] = __float_as_uint(va.y);
                af[mt][2] = __float_as_uint(va.z); af[mt][3] = __float_as_uint(va.w);
            }
            #pragma unroll
            for (int nt = 0; nt < 8; nt++) {
                float2 vb = *(const float2*)&Bs[s * 1024 + (wng + nt) * 64 + lane * 2];
                bf[nt][0] = __float_as_uint(vb.x); bf[nt][1] = __float_as_uint(vb.y);
            }
            #pragma unroll
            for (int mt = 0; mt < 4; mt++)
                #pragma unroll
                for (int nt = 0; nt < 8; nt++)
                    mma8(acc[mt][nt], af[mt], bf[nt]);
        }
        buf++; if (buf == 3) buf = 0;
    }
    #undef STAGE

    const int wm = (warp >> 1) * 64;
    const int wn = (warp & 1) * 64;
    #pragma unroll
    for (int mt = 0; mt < 4; mt++)
        #pragma unroll
        for (int nt = 0; nt < 8; nt++) {
            const int row = bm + wm + mt * 16 + g;
            const int col = bn + wn + nt * 8 + 2 * t;
            *(float2*)&Cm[(size_t)row * N + col] =
                make_float2(acc[mt][nt][0], acc[mt][nt][1]);
            *(float2*)&Cm[(size_t)(row + 8) * N + col] =
                make_float2(acc[mt][nt][2], acc[mt][nt][3]);
        }
}

// ============================================================
// Flash-style warp-autonomous causal attention per (b, h).
// 256 threads = 8 warps; warp w owns 16-row q-strips {w, 15-w}
// (balanced causal work). Online softmax in registers; P via
// register shuffles; single __syncthreads after staging.
// Output written in A-perm layout for the proj GEMM.
// ============================================================
#define QSS 68
#define KSS 72
#define ATTN_SMEM_FLOATS (TT*QSS + TT*KSS + TT*KSS)   // 54272
#define ATTN_SMEM_BYTES  (ATTN_SMEM_FLOATS * 4)        // 217088

__global__ __launch_bounds__(256, 1)
void attn_kernel(const float* __restrict__ qkv, float* __restrict__ att)
{
    extern __shared__ __align__(16) float smf[];
    float* Qs = smf;                 // [256][68]
    float* Ks = Qs + TT * QSS;       // [256][72]
    float* Vs = Ks + TT * KSS;       // [256][72]

    const int tid  = threadIdx.x;
    const int lane = tid & 31;
    const int warp = tid >> 5;
    const int g = lane >> 2;         // 0..7
    const int t = lane & 3;          // 0..3

    const int b = blockIdx.x / HH;
    const int h = blockIdx.x % HH;
    const float* base = qkv + (size_t)b * TT * LDQKV;
    const float scale = 0.05103103630798288f;  // 384^-0.5 (full-embed quirk)

    // ---- Stage Q, K, V as [tok][d], tf32-rounded ----
    {
        const int d4 = (tid & 15) * 4;
        for (int tok = tid >> 4; tok < TT; tok += 16) {
            const float* row = base + (size_t)tok * LDQKV + h * DD + d4;
            float4 kv = *(const float4*)(row);             // K at offset 0
            kv.x = tf32_big(kv.x); kv.y = tf32_big(kv.y);
            kv.z = tf32_big(kv.z); kv.w = tf32_big(kv.w);
            *(float4*)&Ks[tok * KSS + d4] = kv;
            float4 qv = *(const float4*)(row + CC);        // Q at offset C
            qv.x = tf32_big(qv.x); qv.y = tf32_big(qv.y);
            qv.z = tf32_big(qv.z); qv.w = tf32_big(qv.w);
            *(float4*)&Qs[tok * QSS + d4] = qv;
            float4 vv = *(const float4*)(row + 2 * CC);    // V at offset 2C
            vv.x = tf32_big(vv.x); vv.y = tf32_big(vv.y);
            vv.z = tf32_big(vv.z); vv.w = tf32_big(vv.w);
            *(float4*)&Vs[tok * KSS + d4] = vv;
        }
    }
    __syncthreads();   // the ONLY block barrier

    const int srcA = (lane & ~3) | (t >> 1);
    const int srcB = srcA + 2;
    const bool odd = (t & 1) != 0;

    #pragma unroll
    for (int sp = 0; sp < 2; sp++) {
        const int st = sp ? (15 - warp) : warp;    // strip 0..15
        const int rb = st * 16;                    // row base
        const int ktmax = st >> 2;                 // last k-tile (diagonal)

        // ---- Q fragments for this strip (hoisted) ----
        uint32_t qa[8][4];
        #pragma unroll
        for (int s = 0; s < 8; s++) {
            const int r0 = (rb + g) * QSS + 8 * s + t;
            qa[s][0] = __float_as_uint(Qs[r0]);
            qa[s][1] = __float_as_uint(Qs[r0 + 8 * QSS]);
            qa[s][2] = __float_as_uint(Qs[r0 + 4]);
            qa[s][3] = __float_as_uint(Qs[r0 + 8 * QSS + 4]);
        }

        float m0 = -1e30f, m1 = -1e30f, l0 = 0.f, l1 = 0.f;
        float o[8][4];
        #pragma unroll
        for (int j = 0; j < 8; j++)
            #pragma unroll
            for (int e = 0; e < 4; e++) o[j][e] = 0.f;

        for (int kt = 0; kt <= ktmax; kt++) {
            const bool diag = (kt == ktmax);
            const int jn = diag ? 2 * (st & 3) + 2 : 8;   // valid 8-col frags
            const int kbase = kt * 64;

            // ---- S = Qstrip @ Ktile^T (frags sc[j]) ----
            float sc[8][4];
            #pragma unroll
            for (int j = 0; j < 8; j++)
                #pragma unroll
                for (int e = 0; e < 4; e++) sc[j][e] = 0.f;

            #pragma unroll
            for (int s = 0; s < 8; s++) {
                #pragma unroll
                for (int j = 0; j < 8; j++) {
                    if (j < jn) {
                        const int kr = (kbase + 8 * j + g) * KSS + 8 * s + t;
                        uint32_t kb[2];
                        kb[0] = __float_as_uint(Ks[kr]);
                        kb[1] = __float_as_uint(Ks[kr + 4]);
                        mma8(sc[j], qa[s], kb);
                    }
                }
            }

            // ---- causal mask on the diagonal tile ----
            if (diag) {
                const int R0 = rb + g, R1 = R0 + 8;
                #pragma unroll
                for (int j = 0; j < 8; j++) {
                    if (j < jn) {
                        const int Cl = kbase + 8 * j + 2 * t;
                        if (Cl     > R0) sc[j][0] = -1e30f;
                        if (Cl + 1 > R0) sc[j][1] = -1e30f;
                        if (Cl     > R1) sc[j][2] = -1e30f;
                        if (Cl + 1 > R1) sc[j][3] = -1e30f;
                    }
                }
            }

            // ---- online softmax ----
            float mx0 = -1e30f, mx1 = -1e30f;
            #pragma unroll
            for (int j = 0; j < 8; j++) {
                if (j < jn) {
                    mx0 = fmaxf(mx0, fmaxf(sc[j][0], sc[j][1]));
                    mx1 = fmaxf(mx1, fmaxf(sc[j][2], sc[j][3]));
                }
            }
            #pragma unroll
            for (int ofs = 1; ofs <= 2; ofs <<= 1) {
                mx0 = fmaxf(mx0, __shfl_xor_sync(0xffffffffu, mx0, ofs));
                mx1 = fmaxf(mx1, __shfl_xor_sync(0xffffffffu, mx1, ofs));
            }
            mx0 *= scale; mx1 *= scale;
            const float mn0 = fmaxf(m0, mx0), mn1 = fmaxf(m1, mx1);
            const float al0 = __expf(m0 - mn0), al1 = __expf(m1 - mn1);
            m0 = mn0; m1 = mn1;

            float s0 = 0.f, s1 = 0.f;
            #pragma unroll
            for (int j = 0; j < 8; j++) {
                if (j < jn) {
                    float p0 = __expf(sc[j][0] * scale - m0);
                    float p1 = __expf(sc[j][1] * scale - m0);
                    float p2 = __expf(sc[j][2] * scale - m1);
                    float p3 = __expf(sc[j][3] * scale - m1);
                    s0 += p0 + p1; s1 += p2 + p3;
                    sc[j][0] = tf32_big(p0); sc[j][1] = tf32_big(p1);
                    sc[j][2] = tf32_big(p2); sc[j][3] = tf32_big(p3);
                }
            }
            #pragma unroll
            for (int ofs = 1; ofs <= 2; ofs <<= 1) {
                s0 += __shfl_xor_sync(0xffffffffu, s0, ofs);
                s1 += __shfl_xor_sync(0xffffffffu, s1, ofs);
            }
            l0 = l0 * al0 + s0;
            l1 = l1 * al1 + s1;
            #pragma unroll
            for (int j = 0; j < 8; j++) {
                o[j][0] *= al0; o[j][1] *= al0;
                o[j][2] *= al1; o[j][3] *= al1;
            }

            // ---- O += P @ Vtile (P frags -> A-operand via shuffles) ----
            #pragma unroll
            for (int s = 0; s < 8; s++) {
                if (s < jn) {
                    const float y0 = __shfl_sync(0xffffffffu, sc[s][0], srcA);
                    const float y1 = __shfl_sync(0xffffffffu, sc[s][1], srcA);
                    const float y2 = __shfl_sync(0xffffffffu, sc[s][2], srcA);
                    const float y3 = __shfl_sync(0xffffffffu, sc[s][3], srcA);
                    const float z0 = __shfl_sync(0xffffffffu, sc[s][0], srcB);
                    const float z1 = __shfl_sync(0xffffffffu, sc[s][1], srcB);
                    const float z2 = __shfl_sync(0xffffffffu, sc[s][2], srcB);
                    const float z3 = __shfl_sync(0xffffffffu, sc[s][3], srcB);
                    uint32_t pa[4];
                    pa[0] = __float_as_uint(odd ? y1 : y0);   // P[g][8s+t]
                    pa[1] = __float_as_uint(odd ? y3 : y2);   // P[g+8][8s+t]
                    pa[2] = __float_as_uint(odd ? z1 : z0);   // P[g][8s+4+t]
                    pa[3] = __float_as_uint(odd ? z3 : z2);   // P[g+8][8s+4+t]
                    #pragma unroll
                    for (int j2 = 0; j2 < 8; j2++) {
                        const int vr = (kbase + 8 * s + t) * KSS + 8 * j2 + g;
                        uint32_t vb[2];
                        vb[0] = __float_as_uint(Vs[vr]);
                        vb[1] = __float_as_uint(Vs[vr + 4 * KSS]);
                        mma8(o[j2], pa, vb);
                    }
                }
            }
        }

        // ---- epilogue: O/l, tf32-round, write in A-perm layout ----
        {
            const float r0 = 1.f / l0, r1 = 1.f / l1;
            const int mtile = b * 2 + (st >> 3);
            const int mgrp = st & 7;
            #pragma unroll
            for (int j2 = 0; j2 < 8; j2++) {
                const int col0 = h * DD + 8 * j2 + 2 * t;
                const float v0 = tf32_big(o[j2][0] * r0);
                const float v1 = tf32_big(o[j2][1] * r0);
                const float v2 = tf32_big(o[j2][2] * r1);
                const float v3 = tf32_big(o[j2][3] * r1);
                const int kc = col0 >> 5;
                const int s_ = (col0 >> 3) & 3;
                const int cw0 = col0 & 7;
                const size_t cbase = ((size_t)(mtile * 12 + kc)) * 4096
                                   + s_ * 1024 + mgrp * 128;
                const int lane0 = g * 4 + (cw0 & 3);
                const int reg0  = (cw0 >= 4) ? 2 : 0;
                *(float2*)&att[cbase + lane0 * 4 + reg0] = make_float2(v0, v2);
                const int cw1 = cw0 + 1;
                const int lane1 = g * 4 + (cw1 & 3);
                const int reg1  = (cw1 >= 4) ? 2 : 0;
                *(float2*)&att[cbase + lane1 * 4 + reg1] = make_float2(v1, v3);
            }
        }
    }
}

// ============================================================
extern "C" void kernel_launch(void* const* d_in, const int* in_sizes, int n_in,
                              void* d_out, int out_size)
{
    const float* X     = (const float*)d_in[0];
    const float* Wqkv  = (const float*)d_in[1];
    const float* Wproj = (const float*)d_in[2];
    float* out = (float*)d_out;

    void *p0, *p1, *p2, *p3;
    cudaGetSymbolAddress(&p0, g_qkv);
    cudaGetSymbolAddress(&p1, g_att);
    cudaGetSymbolAddress(&p2, g_pX);
    cudaGetSymbolAddress(&p3, g_pW);
    float* qkv  = (float*)p0;
    float* att  = (float*)p1;
    float* pX   = (float*)p2;
    float* pWq  = (float*)p3;
    float* pWp  = pWq + (size_t)3 * CC * CC;

    cudaFuncSetAttribute(gemm_p, cudaFuncAttributeMaxDynamicSharedMemorySize,
                         GEMM_SMEM_BYTES);
    cudaFuncSetAttribute(attn_kernel, cudaFuncAttributeMaxDynamicSharedMemorySize,
                         ATTN_SMEM_BYTES);

    // 0) permute+round operands
    const int pkA = (BB * TT / 128) * (CC / 32) * 1024;
    perm_a<<<(pkA + 255) / 256, 256>>>(X, pX, BB * TT, CC);
    const int pkB1 = (CC * 3 * CC) / 2;
    perm_b<<<(pkB1 + 255) / 256, 256>>>(Wqkv, pWq, CC, 3 * CC);
    const int pkB2 = (CC * CC) / 2;
    perm_b<<<(pkB2 + 255) / 256, 256>>>(Wproj, pWp, CC, CC);

    // 1) qkv = X @ Wqkv   [32768,1152]
    dim3 g1(3 * CC / 128, BB * TT / 128);       // (9, 256)
    gemm_p<<<g1, 128, GEMM_SMEM_BYTES>>>(pX, pWq, qkv, BB * TT, 3 * CC, CC);

    // 2) flash-style causal attention -> att (A-perm layout)
    attn_kernel<<<BB * HH, 256, ATTN_SMEM_BYTES>>>(qkv, att);

    // 3) out = att @ Wproj [32768,384]
    dim3 g3(CC / 128, BB * TT / 128);           // (3, 256)
    gemm_p<<<g3, 128, GEMM_SMEM_BYTES>>>(att, pWp, out, BB * TT, CC, CC);
}